// round 12
// baseline (speedup 1.0000x reference)
#include <cuda_runtime.h>
#include <cuda_bf16.h>
#include <math.h>
#include <stdint.h>

#define BB 2
#define TT 1024
#define CC 1024
#define HH 16
#define LL 4
#define VV 50257
#define DD 64
#define FF 4096

typedef __nv_bfloat16 bf16;

// ---------------- scratch (device globals) ----------------------------------
__device__ float g_x   [BB*TT*CC];
__device__ float g_qkv [BB*TT*3*CC];
__device__ float g_bqkv[LL*3*CC];
__device__ bf16  g_hh [BB*TT*CC],  g_hl [BB*TT*CC];
__device__ bf16  g_yh [BB*TT*CC],  g_yl [BB*TT*CC];
__device__ bf16  g_h2h[BB*TT*FF],  g_h2l[BB*TT*FF];
__device__ bf16  g_wqkvh[LL*3*CC*CC], g_wqkvl[LL*3*CC*CC];
__device__ bf16  g_woh[LL*CC*CC],     g_wol[LL*CC*CC];
__device__ bf16  g_w1h[LL*FF*CC],     g_w1l[LL*FF*CC];
__device__ bf16  g_w2h[LL*CC*FF],     g_w2l[LL*CC*FF];
__device__ bf16  g_whh[(size_t)VV*CC], g_whl[(size_t)VV*CC];

// ---------------- helpers ----------------------------------------------------
__device__ __forceinline__ uint32_t smem_u32(const void* p) {
    uint32_t a;
    asm("{ .reg .u64 t; cvta.to.shared.u64 t, %1; cvt.u32.u64 %0, t; }"
        : "=r"(a) : "l"(p));
    return a;
}
#define CP_ASYNC16(dst, src, sz) \
    asm volatile("cp.async.cg.shared.global [%0], [%1], 16, %2;" \
                 :: "r"(dst), "l"(src), "r"(sz) : "memory")
#define CP_COMMIT() asm volatile("cp.async.commit_group;" ::: "memory")
#define CP_WAIT1()  asm volatile("cp.async.wait_group 1;" ::: "memory")
#define CP_WAIT0()  asm volatile("cp.async.wait_group 0;" ::: "memory")

#define LDSM4(r0, r1, r2, r3, a) \
    asm volatile("ldmatrix.sync.aligned.m8n8.x4.shared.b16 {%0,%1,%2,%3}, [%4];" \
                 : "=r"(r0), "=r"(r1), "=r"(r2), "=r"(r3) : "r"(a))

__device__ __forceinline__ void split2(float x, bf16& h, bf16& l) {
    h = __float2bfloat16(x);
    l = __float2bfloat16(x - __bfloat162float(h));
}

__device__ __forceinline__ void mma_bf16(float* c,
        uint32_t a0, uint32_t a1, uint32_t a2, uint32_t a3,
        uint32_t b0, uint32_t b1) {
    asm volatile("mma.sync.aligned.m16n8k16.row.col.f32.bf16.bf16.f32 "
                 "{%0,%1,%2,%3}, {%4,%5,%6,%7}, {%8,%9}, {%0,%1,%2,%3};"
                 : "+f"(c[0]), "+f"(c[1]), "+f"(c[2]), "+f"(c[3])
                 : "r"(a0), "r"(a1), "r"(a2), "r"(a3), "r"(b0), "r"(b1));
}

// ---------------- GEMM: C = A·B^T via bf16x2 3-term, ldmatrix fragments ------
// 128x128 tile, BK=32, 8 warps (4x2), warp 32x64. 2-stage cp.async.
#define SROWB  80         // 40 bf16 per smem row (padded)
#define PLANEB 10240      // 128*80
#define STAGEB 40960      // 4 planes (Ah, Al, Bh, Bl)
#define GEMM_SMEM (2*STAGEB)

template<bool BIAS, bool RES, bool GELU_, bool POUT>
__global__ void __launch_bounds__(256, 2)
gemm_mma(const bf16* __restrict__ Ah, const bf16* __restrict__ Al,
         const bf16* __restrict__ Bh, const bf16* __restrict__ Bl,
         const float* __restrict__ bias, const float* __restrict__ resid,
         float* __restrict__ Cf, bf16* __restrict__ Ch, bf16* __restrict__ Cl,
         int M, int N, int K) {
    extern __shared__ char sm[];
    const uint32_t sbase = smem_u32(sm);
    const int tid = threadIdx.x, lane = tid & 31, wid = tid >> 5;
    const int gr = lane >> 2, qc = lane & 3;
    const int warp_m = wid >> 1, warp_n = wid & 1;
    const int m0 = blockIdx.y * 128, n0 = blockIdx.x * 128;

    // loader: plane p = tid>>6 (Ah,Al,Bh,Bl), rows lr and lr+64, 4x16B chunks
    const int lp = tid >> 6, lr = tid & 63;
    const bf16* plane = (lp == 0) ? Ah : (lp == 1) ? Al : (lp == 2) ? Bh : Bl;
    const bool aP = lp < 2;
    int r0 = (aP ? m0 : n0) + lr;
    int r1 = r0 + 64;
    const uint32_t sz0 = (aP || r0 < N) ? 16u : 0u;
    const uint32_t sz1 = (aP || r1 < N) ? 16u : 0u;
    if (!aP) { if (r0 >= N) r0 = n0; if (r1 >= N) r1 = n0; }
    const char* src0 = (const char*)(plane + (size_t)r0 * K);
    const char* src1 = (const char*)(plane + (size_t)r1 * K);
    const uint32_t d0b = sbase + lp * PLANEB + lr * SROWB;
    const uint32_t d1b = d0b + 64 * SROWB;

    // ldmatrix base addresses (per lane): row = laneRow, k-half = lane>>4
    const int laneRow = lane & 15;
    const uint32_t khalf = (uint32_t)(lane >> 4) * 16;
    uint32_t baseA[2], baseB[4];
    #pragma unroll
    for (int mt = 0; mt < 2; mt++)
        baseA[mt] = sbase + (uint32_t)(warp_m * 32 + mt * 16 + laneRow) * SROWB + khalf;
    #pragma unroll
    for (int g2 = 0; g2 < 4; g2++)
        baseB[g2] = sbase + 2 * PLANEB +
                    (uint32_t)(warp_n * 64 + g2 * 16 + laneRow) * SROWB + khalf;

    float c[2][8][4];
    #pragma unroll
    for (int mt = 0; mt < 2; mt++)
        #pragma unroll
        for (int nt = 0; nt < 8; nt++)
            #pragma unroll
            for (int r = 0; r < 4; r++) c[mt][nt][r] = 0.f;

    const int NK = K >> 5;

    #pragma unroll
    for (int cc2 = 0; cc2 < 4; cc2++) {
        CP_ASYNC16(d0b + cc2 * 16, src0 + cc2 * 16, sz0);
        CP_ASYNC16(d1b + cc2 * 16, src1 + cc2 * 16, sz1);
    }
    CP_COMMIT();

    for (int i = 0; i < NK; i++) {
        const int s = i & 1;
        if (i + 1 < NK) {
            const int kb = (i + 1) * 64;
            const uint32_t ds = (uint32_t)(s ^ 1) * STAGEB;
            #pragma unroll
            for (int cc2 = 0; cc2 < 4; cc2++) {
                CP_ASYNC16(d0b + ds + cc2 * 16, src0 + kb + cc2 * 16, sz0);
                CP_ASYNC16(d1b + ds + cc2 * 16, src1 + kb + cc2 * 16, sz1);
            }
            CP_COMMIT();
            CP_WAIT1();
        } else {
            CP_WAIT0();
        }
        __syncthreads();

        const uint32_t so = (uint32_t)s * STAGEB;
        #pragma unroll
        for (int ks = 0; ks < 2; ks++) {
            const uint32_t ko = so + ks * 32;
            uint32_t ah[2][4], al2[2][4], bh[8][2], bl2[8][2];
            #pragma unroll
            for (int mt = 0; mt < 2; mt++) {
                LDSM4(ah[mt][0], ah[mt][1], ah[mt][2], ah[mt][3], baseA[mt] + ko);
                LDSM4(al2[mt][0], al2[mt][1], al2[mt][2], al2[mt][3],
                      baseA[mt] + ko + PLANEB);
            }
            #pragma unroll
            for (int g2 = 0; g2 < 4; g2++) {
                uint32_t t0, t1, t2, t3;
                LDSM4(t0, t1, t2, t3, baseB[g2] + ko);
                bh[2*g2][0] = t0; bh[2*g2+1][0] = t1;
                bh[2*g2][1] = t2; bh[2*g2+1][1] = t3;
                LDSM4(t0, t1, t2, t3, baseB[g2] + ko + PLANEB);
                bl2[2*g2][0] = t0; bl2[2*g2+1][0] = t1;
                bl2[2*g2][1] = t2; bl2[2*g2+1][1] = t3;
            }
            #pragma unroll
            for (int mt = 0; mt < 2; mt++)
                #pragma unroll
                for (int nt = 0; nt < 8; nt++)
                    mma_bf16(c[mt][nt], ah[mt][0], ah[mt][1], ah[mt][2], ah[mt][3],
                             bh[nt][0], bh[nt][1]);
            #pragma unroll
            for (int mt = 0; mt < 2; mt++)
                #pragma unroll
                for (int nt = 0; nt < 8; nt++)
                    mma_bf16(c[mt][nt], ah[mt][0], ah[mt][1], ah[mt][2], ah[mt][3],
                             bl2[nt][0], bl2[nt][1]);
            #pragma unroll
            for (int mt = 0; mt < 2; mt++)
                #pragma unroll
                for (int nt = 0; nt < 8; nt++)
                    mma_bf16(c[mt][nt], al2[mt][0], al2[mt][1], al2[mt][2], al2[mt][3],
                             bh[nt][0], bh[nt][1]);
        }
        __syncthreads();
    }

    // epilogue
    #pragma unroll
    for (int mt = 0; mt < 2; mt++) {
        #pragma unroll
        for (int nt = 0; nt < 8; nt++) {
            #pragma unroll
            for (int half = 0; half < 2; half++) {
                const int m = m0 + warp_m * 32 + mt * 16 + gr + half * 8;
                #pragma unroll
                for (int e = 0; e < 2; e++) {
                    const int n = n0 + warp_n * 64 + nt * 8 + qc * 2 + e;
                    if (n < N) {
                        float v = c[mt][nt][half * 2 + e];
                        if (BIAS)  v += bias[n];
                        if (RES)   v += resid[(size_t)m * N + n];
                        if (GELU_) v = 0.5f * v * (1.0f + erff(v * 0.70710678118654752f));
                        if (POUT) {
                            bf16 hh2, ll2; split2(v, hh2, ll2);
                            Ch[(size_t)m * N + n] = hh2;
                            Cl[(size_t)m * N + n] = ll2;
                        } else {
                            Cf[(size_t)m * N + n] = v;
                        }
                    }
                }
            }
        }
    }
}

// ---------------- weight conversion (vectorized x4) --------------------------
__device__ __forceinline__ uint32_t pack2(float x, float y) {
    bf16 hx = __float2bfloat16(x), hy = __float2bfloat16(y);
    return ((uint32_t)__bfloat16_as_ushort(hy) << 16) | __bfloat16_as_ushort(hx);
}
__device__ __forceinline__ void conv4(float4 v, uint2& h, uint2& l) {
    bf16 hx = __float2bfloat16(v.x), hy = __float2bfloat16(v.y);
    bf16 hz = __float2bfloat16(v.z), hw = __float2bfloat16(v.w);
    h.x = ((uint32_t)__bfloat16_as_ushort(hy) << 16) | __bfloat16_as_ushort(hx);
    h.y = ((uint32_t)__bfloat16_as_ushort(hw) << 16) | __bfloat16_as_ushort(hz);
    l.x = pack2(v.x - __bfloat162float(hx), v.y - __bfloat162float(hy));
    l.y = pack2(v.z - __bfloat162float(hz), v.w - __bfloat162float(hw));
}
__global__ void convert_plane(const float* __restrict__ src,
                              bf16* __restrict__ dh, bf16* __restrict__ dl,
                              size_t n4) {
    size_t i = (size_t)blockIdx.x * 256 + threadIdx.x;
    if (i < n4) {
        uint2 h, l;
        conv4(((const float4*)src)[i], h, l);
        ((uint2*)dh)[i] = h;
        ((uint2*)dl)[i] = l;
    }
}
__global__ void convert_qkv(const float* __restrict__ src,
                            bf16* __restrict__ dh, bf16* __restrict__ dl,
                            int which) {
    const size_t seg4 = (size_t)CC * CC / 4;
    size_t i = (size_t)blockIdx.x * 256 + threadIdx.x;
    if (i < (size_t)LL * seg4) {
        size_t layer = i / seg4, rest = i % seg4;
        size_t o = layer * 3 * seg4 + (size_t)which * seg4 + rest;
        uint2 h, l;
        conv4(((const float4*)src)[i], h, l);
        ((uint2*)dh)[o] = h;
        ((uint2*)dl)[o] = l;
    }
}
__global__ void concat_bias(const float* __restrict__ bq, const float* __restrict__ bk,
                            const float* __restrict__ bv, float* __restrict__ dst) {
    int i = blockIdx.x * 256 + threadIdx.x;
    if (i < LL * 3 * CC) {
        int l = i / (3 * CC), r = i % (3 * CC);
        float v = (r < CC) ? bq[l * CC + r]
                : (r < 2 * CC) ? bk[l * CC + r - CC]
                : bv[l * CC + r - 2 * CC];
        dst[i] = v;
    }
}

// ---------------- embedding --------------------------------------------------
__global__ void embed_kernel(const int* __restrict__ idx,
                             const float* __restrict__ tok,
                             const float* __restrict__ pos,
                             float* __restrict__ x) {
    int i = blockIdx.x * blockDim.x + threadIdx.x;
    if (i < BB * TT * CC) {
        int c = i % CC, bt = i / CC, t = bt % TT;
        x[i] = tok[(size_t)idx[bt] * CC + c] + pos[(size_t)t * CC + c];
    }
}

// ---------------- layernorm -> bf16 planes -----------------------------------
__global__ void ln_kernel(const float* __restrict__ in,
                          bf16* __restrict__ oh, bf16* __restrict__ ol,
                          const float* __restrict__ w, const float* __restrict__ b) {
    const int row = blockIdx.x, tid = threadIdx.x;
    const float4 x4 = *(const float4*)(in + (size_t)row * CC + tid * 4);
    __shared__ float red[256];
    red[tid] = x4.x + x4.y + x4.z + x4.w;
    __syncthreads();
    for (int o = 128; o > 0; o >>= 1) { if (tid < o) red[tid] += red[tid + o]; __syncthreads(); }
    const float mu = red[0] * (1.0f / CC);
    __syncthreads();
    const float d0 = x4.x - mu, d1 = x4.y - mu, d2 = x4.z - mu, d3 = x4.w - mu;
    red[tid] = d0 * d0 + d1 * d1 + d2 * d2 + d3 * d3;
    __syncthreads();
    for (int o = 128; o > 0; o >>= 1) { if (tid < o) red[tid] += red[tid + o]; __syncthreads(); }
    const float rstd = rsqrtf(red[0] * (1.0f / CC) + 1e-5f);
    const float4 w4 = *(const float4*)(w + tid * 4);
    const float4 b4 = *(const float4*)(b + tid * 4);
    float4 v;
    v.x = d0 * rstd * w4.x + b4.x;
    v.y = d1 * rstd * w4.y + b4.y;
    v.z = d2 * rstd * w4.z + b4.z;
    v.w = d3 * rstd * w4.w + b4.w;
    uint2 h, l;
    conv4(v, h, l);
    const size_t o4 = ((size_t)row * CC + tid * 4) >> 2;
    ((uint2*)oh)[o4] = h;
    ((uint2*)ol)[o4] = l;
}

// ---------------- attention: 8 q-rows per block, chunked K/V -----------------
#define QT 8
#define JCH 128
#define KVROW 68
#define ATTN_SMEM ((QT*KVROW + JCH*KVROW + QT*TT + 4*QT*DD + 8) * 4)

__global__ void __launch_bounds__(256)
attn_kernel(const float* __restrict__ qkv, bf16* __restrict__ yh, bf16* __restrict__ yl) {
    extern __shared__ float sf[];
    float* qs   = sf;
    float* kv   = sf + QT * KVROW;
    float* sc   = kv + JCH * KVROW;
    float* part = sc + QT * TT;
    float* invs = part + 4 * QT * DD;

    const int tid = threadIdx.x, lane = tid & 31, wid = tid >> 5;
    const int qb = blockIdx.x * QT;
    const int bh = blockIdx.y, b = bh / HH, h = bh % HH;
    const int RS = 3 * CC;
    const float* qp = qkv + (size_t)(b * TT) * RS + h * DD;
    const float* kp = qp + CC;
    const float* vp = qp + 2 * CC;
    const int lenmax = qb + QT;

    for (int i = tid; i < QT * 16; i += 256) {
        int r = i >> 4, d4 = i & 15;
        *(float4*)(qs + r * KVROW + 4 * d4) =
            *(const float4*)(qp + (size_t)(qb + r) * RS + 4 * d4);
    }

    for (int jt = 0; jt < lenmax; jt += JCH) {
        const int nr = min(JCH, lenmax - jt);
        __syncthreads();
        for (int i = tid; i < nr * 16; i += 256) {
            int r = i >> 4, d4 = i & 15;
            *(float4*)(kv + r * KVROW + 4 * d4) =
                *(const float4*)(kp + (size_t)(jt + r) * RS + 4 * d4);
        }
        __syncthreads();
        #pragma unroll
        for (int it = 0; it < 4; it++) {
            const int jj = (tid >> 3) + 32 * it;
            if (jj < nr) {
                const int r = tid & 7;
                const float* kr = kv + jj * KVROW;
                const float* qr = qs + r * KVROW;
                float dot = 0.f;
                #pragma unroll
                for (int d = 0; d < DD; d += 4) {
                    float4 kk = *(const float4*)(kr + d);
                    float4 qq = *(const float4*)(qr + d);
                    dot += kk.x * qq.x + kk.y * qq.y + kk.z * qq.z + kk.w * qq.w;
                }
                sc[r * TT + jt + jj] = dot * 0.125f;
            }
        }
    }
    __syncthreads();

    {
        const int r = wid;
        const int len = qb + r + 1;
        float mx = -1e30f;
        for (int j = lane; j < len; j += 32) mx = fmaxf(mx, sc[r * TT + j]);
        #pragma unroll
        for (int o = 16; o; o >>= 1) mx = fmaxf(mx, __shfl_xor_sync(~0u, mx, o));
        float sum = 0.f;
        for (int j = lane; j < len; j += 32) {
            float e = __expf(sc[r * TT + j] - mx);
            sc[r * TT + j] = e;
            sum += e;
        }
        #pragma unroll
        for (int o = 16; o; o >>= 1) sum += __shfl_xor_sync(~0u, sum, o);
        for (int j = len + lane; j < lenmax; j += 32) sc[r * TT + j] = 0.f;
        if (lane == 0) invs[r] = 1.0f / sum;
    }
    __syncthreads();

    const int g = tid >> 6;
    const int d = tid & 63;
    float acc[QT];
    #pragma unroll
    for (int r = 0; r < QT; r++) acc[r] = 0.f;

    for (int jt = 0; jt < lenmax; jt += JCH) {
        const int nr = min(JCH, lenmax - jt);
        __syncthreads();
        for (int i = tid; i < nr * 16; i += 256) {
            int r = i >> 4, d4 = i & 15;
            *(float4*)(kv + r * KVROW + 4 * d4) =
                *(const float4*)(vp + (size_t)(jt + r) * RS + 4 * d4);
        }
        __syncthreads();
        for (int jj = g; jj < nr; jj += 4) {
            const float vv = kv[jj * KVROW + d];
            const int j = jt + jj;
            #pragma unroll
            for (int r = 0; r < QT; r++)
                acc[r] = fmaf(sc[r * TT + j], vv, acc[r]);
        }
    }
    #pragma unroll
    for (int r = 0; r < QT; r++) part[(g * QT + r) * DD + d] = acc[r];
    __syncthreads();

    for (int i = tid; i < QT * DD; i += 256) {
        const int r = i >> 6, dd = i & 63;
        const float v = (part[(0 * QT + r) * DD + dd] + part[(1 * QT + r) * DD + dd] +
                         part[(2 * QT + r) * DD + dd] + part[(3 * QT + r) * DD + dd]) * invs[r];
        const size_t o = (size_t)(b * TT + qb + r) * CC + h * DD + dd;
        bf16 hh2, ll2; split2(v, hh2, ll2);
        yh[o] = hh2; yl[o] = ll2;
    }
}

// ---------------- host orchestration ---------------------------------------
static inline dim3 tc_grid(int M, int N) {
    return dim3((N + 127) / 128, (M + 127) / 128);
}

extern "C" void kernel_launch(void* const* d_in, const int* in_sizes, int n_in,
                              void* d_out, int out_size) {
    const int*   idx    = (const int*)  d_in[0];
    const float* tok    = (const float*)d_in[1];
    const float* pos    = (const float*)d_in[2];
    const float* ln1w   = (const float*)d_in[3];
    const float* ln1b   = (const float*)d_in[4];
    const float* Wq     = (const float*)d_in[5];
    const float* bq     = (const float*)d_in[6];
    const float* Wk     = (const float*)d_in[7];
    const float* bk     = (const float*)d_in[8];
    const float* Wv     = (const float*)d_in[9];
    const float* bv     = (const float*)d_in[10];
    const float* Wo     = (const float*)d_in[11];
    const float* bo     = (const float*)d_in[12];
    const float* ln2w   = (const float*)d_in[13];
    const float* ln2b   = (const float*)d_in[14];
    const float* W1     = (const float*)d_in[15];
    const float* b1     = (const float*)d_in[16];
    const float* W2     = (const float*)d_in[17];
    const float* b2     = (const float*)d_in[18];
    const float* lnfw   = (const float*)d_in[19];
    const float* lnfb   = (const float*)d_in[20];
    const float* head_w = (const float*)d_in[21];
    float* out = (float*)d_out;

    float *x, *qkv, *bqkv;
    bf16 *hh, *hl, *yh, *yl, *h2h, *h2l;
    bf16 *wqkvh, *wqkvl, *woh, *wol, *w1h, *w1l, *w2h, *w2l, *whh, *whl;
    cudaGetSymbolAddress((void**)&x,     g_x);
    cudaGetSymbolAddress((void**)&qkv,   g_qkv);
    cudaGetSymbolAddress((void**)&bqkv,  g_bqkv);
    cudaGetSymbolAddress((void**)&hh,    g_hh);
    cudaGetSymbolAddress((void**)&hl,    g_hl);
    cudaGetSymbolAddress((void**)&yh,    g_yh);
    cudaGetSymbolAddress((void**)&yl,    g_yl);
    cudaGetSymbolAddress((void**)&h2h,   g_h2h);
    cudaGetSymbolAddress((void**)&h2l,   g_h2l);
    cudaGetSymbolAddress((void**)&wqkvh, g_wqkvh);
    cudaGetSymbolAddress((void**)&wqkvl, g_wqkvl);
    cudaGetSymbolAddress((void**)&woh,   g_woh);
    cudaGetSymbolAddress((void**)&wol,   g_wol);
    cudaGetSymbolAddress((void**)&w1h,   g_w1h);
    cudaGetSymbolAddress((void**)&w1l,   g_w1l);
    cudaGetSymbolAddress((void**)&w2h,   g_w2h);
    cudaGetSymbolAddress((void**)&w2l,   g_w2l);
    cudaGetSymbolAddress((void**)&whh,   g_whh);
    cudaGetSymbolAddress((void**)&whl,   g_whl);

    cudaFuncSetAttribute(gemm_mma<true,  false, false, false>, cudaFuncAttributeMaxDynamicSharedMemorySize, GEMM_SMEM);
    cudaFuncSetAttribute(gemm_mma<true,  true,  false, false>, cudaFuncAttributeMaxDynamicSharedMemorySize, GEMM_SMEM);
    cudaFuncSetAttribute(gemm_mma<true,  false, true,  true >, cudaFuncAttributeMaxDynamicSharedMemorySize, GEMM_SMEM);
    cudaFuncSetAttribute(gemm_mma<false, false, false, false>, cudaFuncAttributeMaxDynamicSharedMemorySize, GEMM_SMEM);
    cudaFuncSetAttribute(attn_kernel, cudaFuncAttributeMaxDynamicSharedMemorySize, ATTN_SMEM);

    const int M = BB * TT;

    {
        size_t seg4 = (size_t)CC * CC / 4;
        int g3 = (int)((LL * seg4 + 255) / 256);
        convert_qkv<<<g3, 256>>>(Wq, wqkvh, wqkvl, 0);
        convert_qkv<<<g3, 256>>>(Wk, wqkvh, wqkvl, 1);
        convert_qkv<<<g3, 256>>>(Wv, wqkvh, wqkvl, 2);
        convert_plane<<<g3, 256>>>(Wo, woh, wol, LL * seg4);
        size_t n1 = (size_t)LL * FF * CC / 4;
        convert_plane<<<(int)((n1 + 255) / 256), 256>>>(W1, w1h, w1l, n1);
        convert_plane<<<(int)((n1 + 255) / 256), 256>>>(W2, w2h, w2l, n1);
        size_t nh = (size_t)VV * CC / 4;
        convert_plane<<<(int)((nh + 255) / 256), 256>>>(head_w, whh, whl, nh);
        concat_bias<<<(LL * 3 * CC + 255) / 256, 256>>>(bq, bk, bv, bqkv);
    }

    embed_kernel<<<(BB * TT * CC + 255) / 256, 256>>>(idx, tok, pos, x);

    for (int l = 0; l < LL; l++) {
        const size_t o3 = (size_t)l * 3 * CC * CC;
        const size_t o1 = (size_t)l * CC * CC;
        const size_t of = (size_t)l * FF * CC;

        ln_kernel<<<M, 256>>>(x, hh, hl, ln1w + (size_t)l * CC, ln1b + (size_t)l * CC);
        gemm_mma<true, false, false, false><<<tc_grid(M, 3 * CC), 256, GEMM_SMEM>>>(
            hh, hl, wqkvh + o3, wqkvl + o3, bqkv + (size_t)l * 3 * CC, nullptr,
            qkv, nullptr, nullptr, M, 3 * CC, CC);
        attn_kernel<<<dim3(TT / QT, BB * HH), 256, ATTN_SMEM>>>(qkv, yh, yl);
        gemm_mma<true, true, false, false><<<tc_grid(M, CC), 256, GEMM_SMEM>>>(
            yh, yl, woh + o1, wol + o1, bo + (size_t)l * CC, x,
            x, nullptr, nullptr, M, CC, CC);
        ln_kernel<<<M, 256>>>(x, hh, hl, ln2w + (size_t)l * CC, ln2b + (size_t)l * CC);
        gemm_mma<true, false, true, true><<<tc_grid(M, FF), 256, GEMM_SMEM>>>(
            hh, hl, w1h + of, w1l + of, b1 + (size_t)l * FF, nullptr,
            nullptr, h2h, h2l, M, FF, CC);
        gemm_mma<true, true, false, false><<<tc_grid(M, CC), 256, GEMM_SMEM>>>(
            h2h, h2l, w2h + of, w2l + of, b2 + (size_t)l * CC, x,
            x, nullptr, nullptr, M, CC, FF);
    }

    ln_kernel<<<M, 256>>>(x, hh, hl, lnfw, lnfb);
    gemm_mma<false, false, false, false><<<tc_grid(M, VV), 256, GEMM_SMEM>>>(
        hh, hl, whh, whl, nullptr, nullptr,
        out, nullptr, nullptr, M, VV, CC);
}

// round 13
// speedup vs baseline: 1.1243x; 1.1243x over previous
#include <cuda_runtime.h>
#include <cuda_bf16.h>
#include <math.h>
#include <stdint.h>

#define BB 2
#define TT 1024
#define CC 1024
#define HH 16
#define LL 4
#define VV 50257
#define DD 64
#define FF 4096

typedef __nv_bfloat16 bf16;

// ---------------- scratch (device globals) ----------------------------------
__device__ float g_x   [BB*TT*CC];
__device__ float g_qkv [BB*TT*3*CC];
__device__ float g_bqkv[LL*3*CC];
__device__ bf16  g_hh [BB*TT*CC],  g_hl [BB*TT*CC];
__device__ bf16  g_yh [BB*TT*CC],  g_yl [BB*TT*CC];
__device__ bf16  g_h2h[BB*TT*FF],  g_h2l[BB*TT*FF];
__device__ bf16  g_wqkvh[LL*3*CC*CC], g_wqkvl[LL*3*CC*CC];
__device__ bf16  g_woh[LL*CC*CC],     g_wol[LL*CC*CC];
__device__ bf16  g_w1h[LL*FF*CC],     g_w1l[LL*FF*CC];
__device__ bf16  g_w2h[LL*CC*FF],     g_w2l[LL*CC*FF];
__device__ bf16  g_whh[(size_t)VV*CC], g_whl[(size_t)VV*CC];

// ---------------- helpers ----------------------------------------------------
__device__ __forceinline__ uint32_t smem_u32(const void* p) {
    uint32_t a;
    asm("{ .reg .u64 t; cvta.to.shared.u64 t, %1; cvt.u32.u64 %0, t; }"
        : "=r"(a) : "l"(p));
    return a;
}
#define CP_ASYNC16(dst, src, sz) \
    asm volatile("cp.async.cg.shared.global [%0], [%1], 16, %2;" \
                 :: "r"(dst), "l"(src), "r"(sz) : "memory")
#define CP_COMMIT() asm volatile("cp.async.commit_group;" ::: "memory")
#define CP_WAIT0()  asm volatile("cp.async.wait_group 0;" ::: "memory")

#define LDSM4(r0, r1, r2, r3, a) \
    asm volatile("ldmatrix.sync.aligned.m8n8.x4.shared.b16 {%0,%1,%2,%3}, [%4];" \
                 : "=r"(r0), "=r"(r1), "=r"(r2), "=r"(r3) : "r"(a))

__device__ __forceinline__ void split2(float x, bf16& h, bf16& l) {
    h = __float2bfloat16(x);
    l = __float2bfloat16(x - __bfloat162float(h));
}

__device__ __forceinline__ void mma_bf16(float* c,
        uint32_t a0, uint32_t a1, uint32_t a2, uint32_t a3,
        uint32_t b0, uint32_t b1) {
    asm volatile("mma.sync.aligned.m16n8k16.row.col.f32.bf16.bf16.f32 "
                 "{%0,%1,%2,%3}, {%4,%5,%6,%7}, {%8,%9}, {%0,%1,%2,%3};"
                 : "+f"(c[0]), "+f"(c[1]), "+f"(c[2]), "+f"(c[3])
                 : "r"(a0), "r"(a1), "r"(a2), "r"(a3), "r"(b0), "r"(b1));
}

// ============================================================================
// gemm_big: 256x128 CTA tile, 8 warps (4m x 2n), warp 64x64, 1 CTA/SM.
// ldmatrix fragments, BK=32, 2-stage cp.async, single sync per chunk.
// ============================================================================
#define BPLANE 10240            // 128*80
#define APLANE 20480            // 256*80
#define BIG_STAGE (2*APLANE + 2*BPLANE)   // 61440
#define BIG_SMEM (2*BIG_STAGE)            // 122880

template<bool BIAS, bool GELU_, bool POUT>
__global__ void __launch_bounds__(256, 1)
gemm_big(const bf16* __restrict__ Ah, const bf16* __restrict__ Al,
         const bf16* __restrict__ Bh, const bf16* __restrict__ Bl,
         const float* __restrict__ bias,
         float* __restrict__ Cf, bf16* __restrict__ Ch, bf16* __restrict__ Cl,
         int M, int N, int K) {
    extern __shared__ char sm[];
    const uint32_t sbase = smem_u32(sm);
    const int tid = threadIdx.x, lane = tid & 31, wid = tid >> 5;
    const int gr = lane >> 2, qc = lane & 3;
    const int warp_m = wid >> 1, warp_n = wid & 1;
    const int m0 = blockIdx.y * 256, n0 = blockIdx.x * 128;

    // ---- loader precompute: row = (tid>>2)+64j, 16B seg = tid&3 ----
    const int lrw = tid >> 2, lsg = tid & 3;
    const size_t rowB = (size_t)K * 2;          // bytes per source row
    const char* aRow0  = (const char*)Ah + (size_t)(m0 + lrw) * rowB + lsg * 16;
    const char* alRow0 = (const char*)Al + (size_t)(m0 + lrw) * rowB + lsg * 16;
    const char* bSrc[2]; const char* blSrc[2]; uint32_t bsz[2];
    #pragma unroll
    for (int j = 0; j < 2; j++) {
        int nrow = n0 + lrw + 64 * j;
        bsz[j] = (nrow < N) ? 16u : 0u;
        if (nrow >= N) nrow = n0;
        bSrc[j]  = (const char*)Bh + (size_t)nrow * rowB + lsg * 16;
        blSrc[j] = (const char*)Bl + (size_t)nrow * rowB + lsg * 16;
    }
    const uint32_t aDst0 = sbase + lrw * 80 + lsg * 16;
    const uint32_t bDst0 = sbase + 2 * APLANE + lrw * 80 + lsg * 16;

    // ---- ldmatrix bases ----
    const int laneRow = lane & 15;
    const uint32_t khalf = (uint32_t)(lane >> 4) * 16;
    uint32_t baseA[4], baseB[4];
    #pragma unroll
    for (int mt = 0; mt < 4; mt++)
        baseA[mt] = sbase + (uint32_t)(warp_m * 64 + mt * 16 + laneRow) * 80 + khalf;
    #pragma unroll
    for (int g2 = 0; g2 < 4; g2++)
        baseB[g2] = sbase + 2 * APLANE +
                    (uint32_t)(warp_n * 64 + g2 * 16 + laneRow) * 80 + khalf;

    float c[4][8][4];
    #pragma unroll
    for (int mt = 0; mt < 4; mt++)
        #pragma unroll
        for (int nt = 0; nt < 8; nt++)
            #pragma unroll
            for (int r = 0; r < 4; r++) c[mt][nt][r] = 0.f;

    const int NK = K >> 5;

    // prefetch chunk 0 into stage 0
    #pragma unroll
    for (int j = 0; j < 4; j++) {
        const size_t so = (size_t)(64 * j) * rowB;
        CP_ASYNC16(aDst0 + j * 5120,          aRow0 + so, 16u);
        CP_ASYNC16(aDst0 + APLANE + j * 5120, alRow0 + so, 16u);
    }
    #pragma unroll
    for (int j = 0; j < 2; j++) {
        CP_ASYNC16(bDst0 + j * 5120,          bSrc[j],  bsz[j]);
        CP_ASYNC16(bDst0 + BPLANE + j * 5120, blSrc[j], bsz[j]);
    }
    CP_COMMIT();

    for (int i = 0; i < NK; i++) {
        const int s = i & 1;
        CP_WAIT0();
        __syncthreads();
        if (i + 1 < NK) {
            const size_t kb = (size_t)(i + 1) * 64;
            const uint32_t ds = (uint32_t)(s ^ 1) * BIG_STAGE;
            #pragma unroll
            for (int j = 0; j < 4; j++) {
                const size_t so = (size_t)(64 * j) * rowB + kb;
                CP_ASYNC16(aDst0 + ds + j * 5120,          aRow0 + so, 16u);
                CP_ASYNC16(aDst0 + ds + APLANE + j * 5120, alRow0 + so, 16u);
            }
            #pragma unroll
            for (int j = 0; j < 2; j++) {
                CP_ASYNC16(bDst0 + ds + j * 5120,          bSrc[j] + kb,  bsz[j]);
                CP_ASYNC16(bDst0 + ds + BPLANE + j * 5120, blSrc[j] + kb, bsz[j]);
            }
            CP_COMMIT();
        }

        const uint32_t so = (uint32_t)s * BIG_STAGE;
        #pragma unroll
        for (int ks = 0; ks < 2; ks++) {
            const uint32_t ko = so + ks * 32;
            uint32_t ah[4][4], al2[4][4], bh[8][2], bl2[8][2];
            #pragma unroll
            for (int mt = 0; mt < 4; mt++) {
                LDSM4(ah[mt][0], ah[mt][1], ah[mt][2], ah[mt][3], baseA[mt] + ko);
                LDSM4(al2[mt][0], al2[mt][1], al2[mt][2], al2[mt][3],
                      baseA[mt] + ko + APLANE);
            }
            #pragma unroll
            for (int g2 = 0; g2 < 4; g2++) {
                uint32_t t0, t1, t2, t3;
                LDSM4(t0, t1, t2, t3, baseB[g2] + ko);
                bh[2*g2][0] = t0; bh[2*g2+1][0] = t1;
                bh[2*g2][1] = t2; bh[2*g2+1][1] = t3;
                LDSM4(t0, t1, t2, t3, baseB[g2] + ko + BPLANE);
                bl2[2*g2][0] = t0; bl2[2*g2+1][0] = t1;
                bl2[2*g2][1] = t2; bl2[2*g2+1][1] = t3;
            }
            #pragma unroll
            for (int mt = 0; mt < 4; mt++)
                #pragma unroll
                for (int nt = 0; nt < 8; nt++)
                    mma_bf16(c[mt][nt], ah[mt][0], ah[mt][1], ah[mt][2], ah[mt][3],
                             bh[nt][0], bh[nt][1]);
            #pragma unroll
            for (int mt = 0; mt < 4; mt++)
                #pragma unroll
                for (int nt = 0; nt < 8; nt++)
                    mma_bf16(c[mt][nt], ah[mt][0], ah[mt][1], ah[mt][2], ah[mt][3],
                             bl2[nt][0], bl2[nt][1]);
            #pragma unroll
            for (int mt = 0; mt < 4; mt++)
                #pragma unroll
                for (int nt = 0; nt < 8; nt++)
                    mma_bf16(c[mt][nt], al2[mt][0], al2[mt][1], al2[mt][2], al2[mt][3],
                             bh[nt][0], bh[nt][1]);
        }
    }

    // epilogue
    #pragma unroll
    for (int mt = 0; mt < 4; mt++) {
        #pragma unroll
        for (int nt = 0; nt < 8; nt++) {
            #pragma unroll
            for (int half = 0; half < 2; half++) {
                const int m = m0 + warp_m * 64 + mt * 16 + gr + half * 8;
                #pragma unroll
                for (int e = 0; e < 2; e++) {
                    const int n = n0 + warp_n * 64 + nt * 8 + qc * 2 + e;
                    if (n < N) {
                        float v = c[mt][nt][half * 2 + e];
                        if (BIAS)  v += bias[n];
                        if (GELU_) v = 0.5f * v * (1.0f + erff(v * 0.70710678118654752f));
                        if (POUT) {
                            bf16 hh2, ll2; split2(v, hh2, ll2);
                            Ch[(size_t)m * N + n] = hh2;
                            Cl[(size_t)m * N + n] = ll2;
                        } else {
                            Cf[(size_t)m * N + n] = v;
                        }
                    }
                }
            }
        }
    }
}

// ============================================================================
// gemm_sm: 128x128 tile, warp 32x64, 2 CTA/SM, scalar LDS fragments (r11 style)
// ============================================================================
#define SROWB  80
#define PLANEB 10240
#define STAGEB 40960
#define SM_SMEM (2*STAGEB)

template<bool BIAS, bool RES>
__global__ void __launch_bounds__(256, 2)
gemm_sm(const bf16* __restrict__ Ah, const bf16* __restrict__ Al,
        const bf16* __restrict__ Bh, const bf16* __restrict__ Bl,
        const float* __restrict__ bias, const float* __restrict__ resid,
        float* __restrict__ Cf, int M, int N, int K) {
    extern __shared__ char sm[];
    const uint32_t sbase = smem_u32(sm);
    const int tid = threadIdx.x, lane = tid & 31, wid = tid >> 5;
    const int gr = lane >> 2, qc = lane & 3;
    const int warp_m = wid >> 1, warp_n = wid & 1;
    const int m0 = blockIdx.y * 128, n0 = blockIdx.x * 128;

    const int lp = tid >> 6, lr = tid & 63;
    const bf16* plane = (lp == 0) ? Ah : (lp == 1) ? Al : (lp == 2) ? Bh : Bl;
    const bool aP = lp < 2;
    int r0 = (aP ? m0 : n0) + lr;
    int r1 = r0 + 64;
    const uint32_t sz0 = (aP || r0 < N) ? 16u : 0u;
    const uint32_t sz1 = (aP || r1 < N) ? 16u : 0u;
    if (!aP) { if (r0 >= N) r0 = n0; if (r1 >= N) r1 = n0; }
    const char* src0 = (const char*)(plane + (size_t)r0 * K);
    const char* src1 = (const char*)(plane + (size_t)r1 * K);
    const uint32_t d0b = sbase + lp * PLANEB + lr * SROWB;
    const uint32_t d1b = d0b + 64 * SROWB;

    float c[2][8][4];
    #pragma unroll
    for (int mt = 0; mt < 2; mt++)
        #pragma unroll
        for (int nt = 0; nt < 8; nt++)
            #pragma unroll
            for (int r = 0; r < 4; r++) c[mt][nt][r] = 0.f;

    const int NK = K >> 5;

    #pragma unroll
    for (int cc2 = 0; cc2 < 4; cc2++) {
        CP_ASYNC16(d0b + cc2 * 16, src0 + cc2 * 16, sz0);
        CP_ASYNC16(d1b + cc2 * 16, src1 + cc2 * 16, sz1);
    }
    CP_COMMIT();

    for (int i = 0; i < NK; i++) {
        const int s = i & 1;
        CP_WAIT0();
        __syncthreads();
        if (i + 1 < NK) {
            const int kb = (i + 1) * 64;
            const uint32_t ds = (uint32_t)(s ^ 1) * STAGEB;
            #pragma unroll
            for (int cc2 = 0; cc2 < 4; cc2++) {
                CP_ASYNC16(d0b + ds + cc2 * 16, src0 + kb + cc2 * 16, sz0);
                CP_ASYNC16(d1b + ds + cc2 * 16, src1 + kb + cc2 * 16, sz1);
            }
            CP_COMMIT();
        }

        const char* st = sm + s * STAGEB;
        #pragma unroll
        for (int ks = 0; ks < 2; ks++) {
            uint32_t ah[2][4], al2[2][4], bh[8][2], bl2[8][2];
            #pragma unroll
            for (int mt = 0; mt < 2; mt++) {
                const int rb = warp_m * 32 + mt * 16 + gr;
                const char* p = st + rb * SROWB + ks * 32 + qc * 4;
                ah[mt][0] = *(const uint32_t*)(p);
                ah[mt][1] = *(const uint32_t*)(p + 8 * SROWB);
                ah[mt][2] = *(const uint32_t*)(p + 16);
                ah[mt][3] = *(const uint32_t*)(p + 8 * SROWB + 16);
                const char* q = p + PLANEB;
                al2[mt][0] = *(const uint32_t*)(q);
                al2[mt][1] = *(const uint32_t*)(q + 8 * SROWB);
                al2[mt][2] = *(const uint32_t*)(q + 16);
                al2[mt][3] = *(const uint32_t*)(q + 8 * SROWB + 16);
            }
            #pragma unroll
            for (int nt = 0; nt < 8; nt++) {
                const int cb = warp_n * 64 + nt * 8 + gr;
                const char* p = st + 2 * PLANEB + cb * SROWB + ks * 32 + qc * 4;
                bh[nt][0]  = *(const uint32_t*)(p);
                bh[nt][1]  = *(const uint32_t*)(p + 16);
                bl2[nt][0] = *(const uint32_t*)(p + PLANEB);
                bl2[nt][1] = *(const uint32_t*)(p + PLANEB + 16);
            }
            #pragma unroll
            for (int mt = 0; mt < 2; mt++)
                #pragma unroll
                for (int nt = 0; nt < 8; nt++)
                    mma_bf16(c[mt][nt], ah[mt][0], ah[mt][1], ah[mt][2], ah[mt][3],
                             bh[nt][0], bh[nt][1]);
            #pragma unroll
            for (int mt = 0; mt < 2; mt++)
                #pragma unroll
                for (int nt = 0; nt < 8; nt++)
                    mma_bf16(c[mt][nt], ah[mt][0], ah[mt][1], ah[mt][2], ah[mt][3],
                             bl2[nt][0], bl2[nt][1]);
            #pragma unroll
            for (int mt = 0; mt < 2; mt++)
                #pragma unroll
                for (int nt = 0; nt < 8; nt++)
                    mma_bf16(c[mt][nt], al2[mt][0], al2[mt][1], al2[mt][2], al2[mt][3],
                             bh[nt][0], bh[nt][1]);
        }
        __syncthreads();
    }

    #pragma unroll
    for (int mt = 0; mt < 2; mt++) {
        #pragma unroll
        for (int nt = 0; nt < 8; nt++) {
            #pragma unroll
            for (int half = 0; half < 2; half++) {
                const int m = m0 + warp_m * 32 + mt * 16 + gr + half * 8;
                #pragma unroll
                for (int e = 0; e < 2; e++) {
                    const int n = n0 + warp_n * 64 + nt * 8 + qc * 2 + e;
                    if (n < N) {
                        float v = c[mt][nt][half * 2 + e];
                        if (BIAS) v += bias[n];
                        if (RES)  v += resid[(size_t)m * N + n];
                        Cf[(size_t)m * N + n] = v;
                    }
                }
            }
        }
    }
}

// ---------------- conversion kernels (exactly 3 launches) --------------------
__device__ __forceinline__ uint32_t pack2(float x, float y) {
    bf16 hx = __float2bfloat16(x), hy = __float2bfloat16(y);
    return ((uint32_t)__bfloat16_as_ushort(hy) << 16) | __bfloat16_as_ushort(hx);
}
__device__ __forceinline__ void conv4(float4 v, uint2& h, uint2& l) {
    bf16 hx = __float2bfloat16(v.x), hy = __float2bfloat16(v.y);
    bf16 hz = __float2bfloat16(v.z), hw = __float2bfloat16(v.w);
    h.x = ((uint32_t)__bfloat16_as_ushort(hy) << 16) | __bfloat16_as_ushort(hx);
    h.y = ((uint32_t)__bfloat16_as_ushort(hw) << 16) | __bfloat16_as_ushort(hz);
    l.x = pack2(v.x - __bfloat162float(hx), v.y - __bfloat162float(hy));
    l.y = pack2(v.z - __bfloat162float(hz), v.w - __bfloat162float(hw));
}
__global__ void convert_qkv_all(const float* __restrict__ Wq, const float* __restrict__ Wk,
                                const float* __restrict__ Wv,
                                bf16* __restrict__ dh, bf16* __restrict__ dl) {
    const size_t seg4 = (size_t)CC * CC / 4;
    size_t i = (size_t)blockIdx.x * 256 + threadIdx.x;
    if (i < 3 * LL * seg4) {
        size_t l = i / (3 * seg4), r = i % (3 * seg4);
        int which = (int)(r / seg4);
        size_t rest = r % seg4;
        const float* src = (which == 0) ? Wq : (which == 1) ? Wk : Wv;
        uint2 h, lo;
        conv4(((const float4*)src)[l * seg4 + rest], h, lo);
        ((uint2*)dh)[i] = h;
        ((uint2*)dl)[i] = lo;
    }
}
__global__ void convert_rest(const float* __restrict__ Wo, const float* __restrict__ W1,
                             const float* __restrict__ W2,
                             bf16* __restrict__ woh, bf16* __restrict__ wol,
                             bf16* __restrict__ w1h, bf16* __restrict__ w1l,
                             bf16* __restrict__ w2h, bf16* __restrict__ w2l) {
    const size_t s0 = (size_t)LL * CC * CC / 4;
    const size_t s1 = (size_t)LL * FF * CC / 4;
    size_t i = (size_t)blockIdx.x * 256 + threadIdx.x;
    const float* src; bf16* dh; bf16* dl; size_t j;
    if (i < s0)           { src = Wo; dh = woh; dl = wol; j = i; }
    else if (i < s0 + s1) { src = W1; dh = w1h; dl = w1l; j = i - s0; }
    else if (i < s0 + 2*s1) { src = W2; dh = w2h; dl = w2l; j = i - s0 - s1; }
    else return;
    uint2 h, lo;
    conv4(((const float4*)src)[j], h, lo);
    ((uint2*)dh)[j] = h;
    ((uint2*)dl)[j] = lo;
}
__global__ void convert_head_bias(const float* __restrict__ head,
                                  bf16* __restrict__ whh, bf16* __restrict__ whl,
                                  const float* __restrict__ bq, const float* __restrict__ bk,
                                  const float* __restrict__ bv, float* __restrict__ bqkv) {
    const size_t n4 = (size_t)VV * CC / 4;
    size_t i = (size_t)blockIdx.x * 256 + threadIdx.x;
    if (i < n4) {
        uint2 h, lo;
        conv4(((const float4*)head)[i], h, lo);
        ((uint2*)whh)[i] = h;
        ((uint2*)whl)[i] = lo;
    }
    if (i < LL * 3 * CC) {
        int l = (int)(i / (3 * CC)), r = (int)(i % (3 * CC));
        float v = (r < CC) ? bq[l * CC + r]
                : (r < 2 * CC) ? bk[l * CC + r - CC]
                : bv[l * CC + r - 2 * CC];
        bqkv[i] = v;
    }
}

// ---------------- embedding --------------------------------------------------
__global__ void embed_kernel(const int* __restrict__ idx,
                             const float* __restrict__ tok,
                             const float* __restrict__ pos,
                             float* __restrict__ x) {
    int i = blockIdx.x * blockDim.x + threadIdx.x;
    if (i < BB * TT * CC) {
        int c = i % CC, bt = i / CC, t = bt % TT;
        x[i] = tok[(size_t)idx[bt] * CC + c] + pos[(size_t)t * CC + c];
    }
}

// ---------------- layernorm -> bf16 planes -----------------------------------
__global__ void ln_kernel(const float* __restrict__ in,
                          bf16* __restrict__ oh, bf16* __restrict__ ol,
                          const float* __restrict__ w, const float* __restrict__ b) {
    const int row = blockIdx.x, tid = threadIdx.x;
    const float4 x4 = *(const float4*)(in + (size_t)row * CC + tid * 4);
    __shared__ float red[256];
    red[tid] = x4.x + x4.y + x4.z + x4.w;
    __syncthreads();
    for (int o = 128; o > 0; o >>= 1) { if (tid < o) red[tid] += red[tid + o]; __syncthreads(); }
    const float mu = red[0] * (1.0f / CC);
    __syncthreads();
    const float d0 = x4.x - mu, d1 = x4.y - mu, d2 = x4.z - mu, d3 = x4.w - mu;
    red[tid] = d0 * d0 + d1 * d1 + d2 * d2 + d3 * d3;
    __syncthreads();
    for (int o = 128; o > 0; o >>= 1) { if (tid < o) red[tid] += red[tid + o]; __syncthreads(); }
    const float rstd = rsqrtf(red[0] * (1.0f / CC) + 1e-5f);
    const float4 w4 = *(const float4*)(w + tid * 4);
    const float4 b4 = *(const float4*)(b + tid * 4);
    float4 v;
    v.x = d0 * rstd * w4.x + b4.x;
    v.y = d1 * rstd * w4.y + b4.y;
    v.z = d2 * rstd * w4.z + b4.z;
    v.w = d3 * rstd * w4.w + b4.w;
    uint2 h, l;
    conv4(v, h, l);
    const size_t o4 = ((size_t)row * CC + tid * 4) >> 2;
    ((uint2*)oh)[o4] = h;
    ((uint2*)ol)[o4] = l;
}

// ---------------- attention: 8 q-rows per block, chunked K/V -----------------
#define QT 8
#define JCH 128
#define KVROW 68
#define ATTN_SMEM ((QT*KVROW + JCH*KVROW + QT*TT + 4*QT*DD + 8) * 4)

__global__ void __launch_bounds__(256)
attn_kernel(const float* __restrict__ qkv, bf16* __restrict__ yh, bf16* __restrict__ yl) {
    extern __shared__ float sf[];
    float* qs   = sf;
    float* kv   = sf + QT * KVROW;
    float* sc   = kv + JCH * KVROW;
    float* part = sc + QT * TT;
    float* invs = part + 4 * QT * DD;

    const int tid = threadIdx.x, lane = tid & 31, wid = tid >> 5;
    const int qb = blockIdx.x * QT;
    const int bh = blockIdx.y, b = bh / HH, h = bh % HH;
    const int RS = 3 * CC;
    const float* qp = qkv + (size_t)(b * TT) * RS + h * DD;
    const float* kp = qp + CC;
    const float* vp = qp + 2 * CC;
    const int lenmax = qb + QT;

    for (int i = tid; i < QT * 16; i += 256) {
        int r = i >> 4, d4 = i & 15;
        *(float4*)(qs + r * KVROW + 4 * d4) =
            *(const float4*)(qp + (size_t)(qb + r) * RS + 4 * d4);
    }

    for (int jt = 0; jt < lenmax; jt += JCH) {
        const int nr = min(JCH, lenmax - jt);
        __syncthreads();
        for (int i = tid; i < nr * 16; i += 256) {
            int r = i >> 4, d4 = i & 15;
            *(float4*)(kv + r * KVROW + 4 * d4) =
                *(const float4*)(kp + (size_t)(jt + r) * RS + 4 * d4);
        }
        __syncthreads();
        #pragma unroll
        for (int it = 0; it < 4; it++) {
            const int jj = (tid >> 3) + 32 * it;
            if (jj < nr) {
                const int r = tid & 7;
                const float* kr = kv + jj * KVROW;
                const float* qr = qs + r * KVROW;
                float dot = 0.f;
                #pragma unroll
                for (int d = 0; d < DD; d += 4) {
                    float4 kk = *(const float4*)(kr + d);
                    float4 qq = *(const float4*)(qr + d);
                    dot += kk.x * qq.x + kk.y * qq.y + kk.z * qq.z + kk.w * qq.w;
                }
                sc[r * TT + jt + jj] = dot * 0.125f;
            }
        }
    }
    __syncthreads();

    {
        const int r = wid;
        const int len = qb + r + 1;
        float mx = -1e30f;
        for (int j = lane; j < len; j += 32) mx = fmaxf(mx, sc[r * TT + j]);
        #pragma unroll
        for (int o = 16; o; o >>= 1) mx = fmaxf(mx, __shfl_xor_sync(~0u, mx, o));
        float sum = 0.f;
        for (int j = lane; j < len; j += 32) {
            float e = __expf(sc[r * TT + j] - mx);
            sc[r * TT + j] = e;
            sum += e;
        }
        #pragma unroll
        for (int o = 16; o; o >>= 1) sum += __shfl_xor_sync(~0u, sum, o);
        for (int j = len + lane; j < lenmax; j += 32) sc[r * TT + j] = 0.f;
        if (lane == 0) invs[r] = 1.0f / sum;
    }
    __syncthreads();

    const int g = tid >> 6;
    const int d = tid & 63;
    float acc[QT];
    #pragma unroll
    for (int r = 0; r < QT; r++) acc[r] = 0.f;

    for (int jt = 0; jt < lenmax; jt += JCH) {
        const int nr = min(JCH, lenmax - jt);
        __syncthreads();
        for (int i = tid; i < nr * 16; i += 256) {
            int r = i >> 4, d4 = i & 15;
            *(float4*)(kv + r * KVROW + 4 * d4) =
                *(const float4*)(vp + (size_t)(jt + r) * RS + 4 * d4);
        }
        __syncthreads();
        for (int jj = g; jj < nr; jj += 4) {
            const float vv = kv[jj * KVROW + d];
            const int j = jt + jj;
            #pragma unroll
            for (int r = 0; r < QT; r++)
                acc[r] = fmaf(sc[r * TT + j], vv, acc[r]);
        }
    }
    #pragma unroll
    for (int r = 0; r < QT; r++) part[(g * QT + r) * DD + d] = acc[r];
    __syncthreads();

    for (int i = tid; i < QT * DD; i += 256) {
        const int r = i >> 6, dd = i & 63;
        const float v = (part[(0 * QT + r) * DD + dd] + part[(1 * QT + r) * DD + dd] +
                         part[(2 * QT + r) * DD + dd] + part[(3 * QT + r) * DD + dd]) * invs[r];
        const size_t o = (size_t)(b * TT + qb + r) * CC + h * DD + dd;
        bf16 hh2, ll2; split2(v, hh2, ll2);
        yh[o] = hh2; yl[o] = ll2;
    }
}

// ---------------- host orchestration ---------------------------------------
static inline dim3 big_grid(int M, int N) {
    return dim3((N + 127) / 128, (M + 255) / 256);
}
static inline dim3 sm_grid(int M, int N) {
    return dim3((N + 127) / 128, (M + 127) / 128);
}

extern "C" void kernel_launch(void* const* d_in, const int* in_sizes, int n_in,
                              void* d_out, int out_size) {
    const int*   idx    = (const int*)  d_in[0];
    const float* tok    = (const float*)d_in[1];
    const float* pos    = (const float*)d_in[2];
    const float* ln1w   = (const float*)d_in[3];
    const float* ln1b   = (const float*)d_in[4];
    const float* Wq     = (const float*)d_in[5];
    const float* bq     = (const float*)d_in[6];
    const float* Wk     = (const float*)d_in[7];
    const float* bk     = (const float*)d_in[8];
    const float* Wv     = (const float*)d_in[9];
    const float* bv     = (const float*)d_in[10];
    const float* Wo     = (const float*)d_in[11];
    const float* bo     = (const float*)d_in[12];
    const float* ln2w   = (const float*)d_in[13];
    const float* ln2b   = (const float*)d_in[14];
    const float* W1     = (const float*)d_in[15];
    const float* b1     = (const float*)d_in[16];
    const float* W2     = (const float*)d_in[17];
    const float* b2     = (const float*)d_in[18];
    const float* lnfw   = (const float*)d_in[19];
    const float* lnfb   = (const float*)d_in[20];
    const float* head_w = (const float*)d_in[21];
    float* out = (float*)d_out;

    float *x, *qkv, *bqkv;
    bf16 *hh, *hl, *yh, *yl, *h2h, *h2l;
    bf16 *wqkvh, *wqkvl, *woh, *wol, *w1h, *w1l, *w2h, *w2l, *whh, *whl;
    cudaGetSymbolAddress((void**)&x,     g_x);
    cudaGetSymbolAddress((void**)&qkv,   g_qkv);
    cudaGetSymbolAddress((void**)&bqkv,  g_bqkv);
    cudaGetSymbolAddress((void**)&hh,    g_hh);
    cudaGetSymbolAddress((void**)&hl,    g_hl);
    cudaGetSymbolAddress((void**)&yh,    g_yh);
    cudaGetSymbolAddress((void**)&yl,    g_yl);
    cudaGetSymbolAddress((void**)&h2h,   g_h2h);
    cudaGetSymbolAddress((void**)&h2l,   g_h2l);
    cudaGetSymbolAddress((void**)&wqkvh, g_wqkvh);
    cudaGetSymbolAddress((void**)&wqkvl, g_wqkvl);
    cudaGetSymbolAddress((void**)&woh,   g_woh);
    cudaGetSymbolAddress((void**)&wol,   g_wol);
    cudaGetSymbolAddress((void**)&w1h,   g_w1h);
    cudaGetSymbolAddress((void**)&w1l,   g_w1l);
    cudaGetSymbolAddress((void**)&w2h,   g_w2h);
    cudaGetSymbolAddress((void**)&w2l,   g_w2l);
    cudaGetSymbolAddress((void**)&whh,   g_whh);
    cudaGetSymbolAddress((void**)&whl,   g_whl);

    cudaFuncSetAttribute(gemm_big<true,  false, false>, cudaFuncAttributeMaxDynamicSharedMemorySize, BIG_SMEM);
    cudaFuncSetAttribute(gemm_big<true,  true,  true >, cudaFuncAttributeMaxDynamicSharedMemorySize, BIG_SMEM);
    cudaFuncSetAttribute(gemm_big<false, false, false>, cudaFuncAttributeMaxDynamicSharedMemorySize, BIG_SMEM);
    cudaFuncSetAttribute(gemm_sm<true, true>,  cudaFuncAttributeMaxDynamicSharedMemorySize, SM_SMEM);
    cudaFuncSetAttribute(attn_kernel, cudaFuncAttributeMaxDynamicSharedMemorySize, ATTN_SMEM);

    const int M = BB * TT;

    // [0..2] weight conversions (3 launches so gemm_big lands at ncu -s 5)
    {
        size_t seg4 = (size_t)CC * CC / 4;
        convert_qkv_all<<<(int)((3 * LL * seg4 + 255) / 256), 256>>>(Wq, Wk, Wv, wqkvh, wqkvl);
        size_t tot = (size_t)LL * CC * CC / 4 + 2 * ((size_t)LL * FF * CC / 4);
        convert_rest<<<(int)((tot + 255) / 256), 256>>>(Wo, W1, W2, woh, wol, w1h, w1l, w2h, w2l);
        size_t nh = (size_t)VV * CC / 4;
        convert_head_bias<<<(int)((nh + 255) / 256), 256>>>(head_w, whh, whl, bq, bk, bv, bqkv);
    }

    // [3] embed
    embed_kernel<<<(BB * TT * CC + 255) / 256, 256>>>(idx, tok, pos, x);

    for (int l = 0; l < LL; l++) {
        const size_t o3 = (size_t)l * 3 * CC * CC;
        const size_t o1 = (size_t)l * CC * CC;
        const size_t of = (size_t)l * FF * CC;

        // [4] ln1  [5] gemm_big qkv  <- profiled at l=0
        ln_kernel<<<M, 256>>>(x, hh, hl, ln1w + (size_t)l * CC, ln1b + (size_t)l * CC);
        gemm_big<true, false, false><<<big_grid(M, 3 * CC), 256, BIG_SMEM>>>(
            hh, hl, wqkvh + o3, wqkvl + o3, bqkv + (size_t)l * 3 * CC,
            qkv, nullptr, nullptr, M, 3 * CC, CC);
        attn_kernel<<<dim3(TT / QT, BB * HH), 256, ATTN_SMEM>>>(qkv, yh, yl);
        gemm_sm<true, true><<<sm_grid(M, CC), 256, SM_SMEM>>>(
            yh, yl, woh + o1, wol + o1, bo + (size_t)l * CC, x, x, M, CC, CC);
        ln_kernel<<<M, 256>>>(x, hh, hl, ln2w + (size_t)l * CC, ln2b + (size_t)l * CC);
        gemm_big<true, true, true><<<big_grid(M, FF), 256, BIG_SMEM>>>(
            hh, hl, w1h + of, w1l + of, b1 + (size_t)l * FF,
            nullptr, h2h, h2l, M, FF, CC);
        gemm_sm<true, true><<<sm_grid(M, CC), 256, SM_SMEM>>>(
            h2h, h2l, w2h + of, w2l + of, b2 + (size_t)l * CC, x, x, M, CC, FF);
    }

    ln_kernel<<<M, 256>>>(x, hh, hl, lnfw, lnfb);
    gemm_big<false, false, false><<<big_grid(M, VV), 256, BIG_SMEM>>>(
        hh, hl, whh, whl, nullptr,
        out, nullptr, nullptr, M, VV, CC);
}

// round 14
// speedup vs baseline: 1.1365x; 1.0108x over previous
#include <cuda_runtime.h>
#include <cuda_bf16.h>
#include <math.h>
#include <stdint.h>

#define BB 2
#define TT 1024
#define CC 1024
#define HH 16
#define LL 4
#define VV 50257
#define DD 64
#define FF 4096

typedef __nv_bfloat16 bf16;

// ---------------- scratch (device globals) ----------------------------------
__device__ float g_x   [BB*TT*CC];
__device__ float g_qkv [BB*TT*3*CC];
__device__ float g_bqkv[LL*3*CC];
__device__ bf16  g_hh [BB*TT*CC],  g_hl [BB*TT*CC];
__device__ bf16  g_yh [BB*TT*CC],  g_yl [BB*TT*CC];
__device__ bf16  g_h2h[BB*TT*FF],  g_h2l[BB*TT*FF];
__device__ bf16  g_wqkvh[LL*3*CC*CC], g_wqkvl[LL*3*CC*CC];
__device__ bf16  g_woh[LL*CC*CC],     g_wol[LL*CC*CC];
__device__ bf16  g_w1h[LL*FF*CC],     g_w1l[LL*FF*CC];
__device__ bf16  g_w2h[LL*CC*FF],     g_w2l[LL*CC*FF];
__device__ bf16  g_whh[(size_t)VV*CC], g_whl[(size_t)VV*CC];

// ---------------- helpers ----------------------------------------------------
__device__ __forceinline__ uint32_t smem_u32(const void* p) {
    uint32_t a;
    asm("{ .reg .u64 t; cvta.to.shared.u64 t, %1; cvt.u32.u64 %0, t; }"
        : "=r"(a) : "l"(p));
    return a;
}
#define CP_ASYNC16(dst, src, sz) \
    asm volatile("cp.async.cg.shared.global [%0], [%1], 16, %2;" \
                 :: "r"(dst), "l"(src), "r"(sz) : "memory")
#define CP_COMMIT() asm volatile("cp.async.commit_group;" ::: "memory")
#define CP_WAIT1()  asm volatile("cp.async.wait_group 1;" ::: "memory")
#define CP_WAIT0()  asm volatile("cp.async.wait_group 0;" ::: "memory")

#define LDSM4(r0, r1, r2, r3, a) \
    asm volatile("ldmatrix.sync.aligned.m8n8.x4.shared.b16 {%0,%1,%2,%3}, [%4];" \
                 : "=r"(r0), "=r"(r1), "=r"(r2), "=r"(r3) : "r"(a))

__device__ __forceinline__ void split2(float x, bf16& h, bf16& l) {
    h = __float2bfloat16(x);
    l = __float2bfloat16(x - __bfloat162float(h));
}
__device__ __forceinline__ float gelu_f(float v) {
    return 0.5f * v * (1.0f + erff(v * 0.70710678118654752f));
}
__device__ __forceinline__ uint32_t packbf(bf16 a, bf16 b) {
    return ((uint32_t)__bfloat16_as_ushort(b) << 16) | __bfloat16_as_ushort(a);
}

__device__ __forceinline__ void mma_bf16(float* c,
        uint32_t a0, uint32_t a1, uint32_t a2, uint32_t a3,
        uint32_t b0, uint32_t b1) {
    asm volatile("mma.sync.aligned.m16n8k16.row.col.f32.bf16.bf16.f32 "
                 "{%0,%1,%2,%3}, {%4,%5,%6,%7}, {%8,%9}, {%0,%1,%2,%3};"
                 : "+f"(c[0]), "+f"(c[1]), "+f"(c[2]), "+f"(c[3])
                 : "r"(a0), "r"(a1), "r"(a2), "r"(a3), "r"(b0), "r"(b1));
}

// ============================================================================
// gemm_big: 256x128 CTA tile, 8 warps (4m x 2n), warp 64x64, 1 CTA/SM.
// ldmatrix fragments, BK=32, 3-stage cp.async pipeline.
// ============================================================================
#define BPLANE 10240            // 128*80
#define APLANE 20480            // 256*80
#define BIG_STAGE (2*APLANE + 2*BPLANE)   // 61440
#define BIG_SMEM (3*BIG_STAGE)            // 184320

template<bool BIAS, bool GELU_, bool POUT>
__global__ void __launch_bounds__(256, 1)
gemm_big(const bf16* __restrict__ Ah, const bf16* __restrict__ Al,
         const bf16* __restrict__ Bh, const bf16* __restrict__ Bl,
         const float* __restrict__ bias,
         float* __restrict__ Cf, bf16* __restrict__ Ch, bf16* __restrict__ Cl,
         int M, int N, int K) {
    extern __shared__ char sm[];
    const uint32_t sbase = smem_u32(sm);
    const int tid = threadIdx.x, lane = tid & 31, wid = tid >> 5;
    const int gr = lane >> 2, qc = lane & 3;
    const int warp_m = wid >> 1, warp_n = wid & 1;
    const int m0 = blockIdx.y * 256, n0 = blockIdx.x * 128;

    // ---- loader precompute: row = (tid>>2)+64j, 16B seg = tid&3 ----
    const int lrw = tid >> 2, lsg = tid & 3;
    const size_t rowB = (size_t)K * 2;          // bytes per source row
    const char* aRow0  = (const char*)Ah + (size_t)(m0 + lrw) * rowB + lsg * 16;
    const char* alRow0 = (const char*)Al + (size_t)(m0 + lrw) * rowB + lsg * 16;
    const char* bSrc[2]; const char* blSrc[2]; uint32_t bsz[2];
    #pragma unroll
    for (int j = 0; j < 2; j++) {
        int nrow = n0 + lrw + 64 * j;
        bsz[j] = (nrow < N) ? 16u : 0u;
        if (nrow >= N) nrow = n0;
        bSrc[j]  = (const char*)Bh + (size_t)nrow * rowB + lsg * 16;
        blSrc[j] = (const char*)Bl + (size_t)nrow * rowB + lsg * 16;
    }
    const uint32_t aDst0 = sbase + lrw * 80 + lsg * 16;
    const uint32_t bDst0 = sbase + 2 * APLANE + lrw * 80 + lsg * 16;

    // ---- ldmatrix bases ----
    const int laneRow = lane & 15;
    const uint32_t khalf = (uint32_t)(lane >> 4) * 16;
    uint32_t baseA[4], baseB[4];
    #pragma unroll
    for (int mt = 0; mt < 4; mt++)
        baseA[mt] = sbase + (uint32_t)(warp_m * 64 + mt * 16 + laneRow) * 80 + khalf;
    #pragma unroll
    for (int g2 = 0; g2 < 4; g2++)
        baseB[g2] = sbase + 2 * APLANE +
                    (uint32_t)(warp_n * 64 + g2 * 16 + laneRow) * 80 + khalf;

    float c[4][8][4];
    #pragma unroll
    for (int mt = 0; mt < 4; mt++)
        #pragma unroll
        for (int nt = 0; nt < 8; nt++)
            #pragma unroll
            for (int r = 0; r < 4; r++) c[mt][nt][r] = 0.f;

    const int NK = K >> 5;   // >= 32 always here

    // prefetch chunks 0,1 into stages 0,1
    #pragma unroll
    for (int pc = 0; pc < 2; pc++) {
        const size_t kb = (size_t)pc * 64;
        const uint32_t ds = (uint32_t)pc * BIG_STAGE;
        #pragma unroll
        for (int j = 0; j < 4; j++) {
            const size_t so = (size_t)(64 * j) * rowB + kb;
            CP_ASYNC16(aDst0 + ds + j * 5120,          aRow0 + so, 16u);
            CP_ASYNC16(aDst0 + ds + APLANE + j * 5120, alRow0 + so, 16u);
        }
        #pragma unroll
        for (int j = 0; j < 2; j++) {
            CP_ASYNC16(bDst0 + ds + j * 5120,          bSrc[j] + kb,  bsz[j]);
            CP_ASYNC16(bDst0 + ds + BPLANE + j * 5120, blSrc[j] + kb, bsz[j]);
        }
        CP_COMMIT();
    }

    int s = 0;
    for (int i = 0; i < NK; i++) {
        if (i + 1 < NK) { CP_WAIT1(); } else { CP_WAIT0(); }
        __syncthreads();
        if (i + 2 < NK) {
            const size_t kb = (size_t)(i + 2) * 64;
            int sn = s + 2; if (sn >= 3) sn -= 3;
            const uint32_t ds = (uint32_t)sn * BIG_STAGE;
            #pragma unroll
            for (int j = 0; j < 4; j++) {
                const size_t so = (size_t)(64 * j) * rowB + kb;
                CP_ASYNC16(aDst0 + ds + j * 5120,          aRow0 + so, 16u);
                CP_ASYNC16(aDst0 + ds + APLANE + j * 5120, alRow0 + so, 16u);
            }
            #pragma unroll
            for (int j = 0; j < 2; j++) {
                CP_ASYNC16(bDst0 + ds + j * 5120,          bSrc[j] + kb,  bsz[j]);
                CP_ASYNC16(bDst0 + ds + BPLANE + j * 5120, blSrc[j] + kb, bsz[j]);
            }
            CP_COMMIT();
        }

        const uint32_t so = (uint32_t)s * BIG_STAGE;
        #pragma unroll
        for (int ks = 0; ks < 2; ks++) {
            const uint32_t ko = so + ks * 32;
            uint32_t ah[4][4], al2[4][4], bh[8][2], bl2[8][2];
            #pragma unroll
            for (int mt = 0; mt < 4; mt++) {
                LDSM4(ah[mt][0], ah[mt][1], ah[mt][2], ah[mt][3], baseA[mt] + ko);
                LDSM4(al2[mt][0], al2[mt][1], al2[mt][2], al2[mt][3],
                      baseA[mt] + ko + APLANE);
            }
            #pragma unroll
            for (int g2 = 0; g2 < 4; g2++) {
                uint32_t t0, t1, t2, t3;
                LDSM4(t0, t1, t2, t3, baseB[g2] + ko);
                bh[2*g2][0] = t0; bh[2*g2+1][0] = t1;
                bh[2*g2][1] = t2; bh[2*g2+1][1] = t3;
                LDSM4(t0, t1, t2, t3, baseB[g2] + ko + BPLANE);
                bl2[2*g2][0] = t0; bl2[2*g2+1][0] = t1;
                bl2[2*g2][1] = t2; bl2[2*g2+1][1] = t3;
            }
            #pragma unroll
            for (int mt = 0; mt < 4; mt++)
                #pragma unroll
                for (int nt = 0; nt < 8; nt++)
                    mma_bf16(c[mt][nt], ah[mt][0], ah[mt][1], ah[mt][2], ah[mt][3],
                             bh[nt][0], bh[nt][1]);
            #pragma unroll
            for (int mt = 0; mt < 4; mt++)
                #pragma unroll
                for (int nt = 0; nt < 8; nt++)
                    mma_bf16(c[mt][nt], ah[mt][0], ah[mt][1], ah[mt][2], ah[mt][3],
                             bl2[nt][0], bl2[nt][1]);
            #pragma unroll
            for (int mt = 0; mt < 4; mt++)
                #pragma unroll
                for (int nt = 0; nt < 8; nt++)
                    mma_bf16(c[mt][nt], al2[mt][0], al2[mt][1], al2[mt][2], al2[mt][3],
                             bh[nt][0], bh[nt][1]);
        }
        s++; if (s == 3) s = 0;
    }

    // epilogue (paired stores; scalar fallback for odd-N head / tail)
    const bool evenN = (N & 1) == 0;
    #pragma unroll
    for (int mt = 0; mt < 4; mt++) {
        #pragma unroll
        for (int nt = 0; nt < 8; nt++) {
            const int n = n0 + warp_n * 64 + nt * 8 + qc * 2;
            #pragma unroll
            for (int half = 0; half < 2; half++) {
                const int m = m0 + warp_m * 64 + mt * 16 + gr + half * 8;
                float v0 = c[mt][nt][half * 2 + 0];
                float v1 = c[mt][nt][half * 2 + 1];
                if (n + 1 < N) {
                    if (BIAS)  { v0 += bias[n]; v1 += bias[n + 1]; }
                    if (GELU_) { v0 = gelu_f(v0); v1 = gelu_f(v1); }
                    if (POUT) {
                        bf16 h0, l0, h1, l1;
                        split2(v0, h0, l0); split2(v1, h1, l1);
                        *(uint32_t*)(Ch + (size_t)m * N + n) = packbf(h0, h1);
                        *(uint32_t*)(Cl + (size_t)m * N + n) = packbf(l0, l1);
                    } else if (evenN) {
                        *(float2*)(Cf + (size_t)m * N + n) = make_float2(v0, v1);
                    } else {
                        Cf[(size_t)m * N + n] = v0;
                        Cf[(size_t)m * N + n + 1] = v1;
                    }
                } else if (n < N) {
                    if (BIAS)  v0 += bias[n];
                    if (GELU_) v0 = gelu_f(v0);
                    if (POUT) {
                        bf16 h0, l0; split2(v0, h0, l0);
                        Ch[(size_t)m * N + n] = h0;
                        Cl[(size_t)m * N + n] = l0;
                    } else {
                        Cf[(size_t)m * N + n] = v0;
                    }
                }
            }
        }
    }
}

// ============================================================================
// gemm_sm: 128x128 tile, warp 32x64, 2 CTA/SM, scalar LDS fragments
// ============================================================================
#define SROWB  80
#define PLANEB 10240
#define STAGEB 40960
#define SM_SMEM (2*STAGEB)

template<bool BIAS, bool RES>
__global__ void __launch_bounds__(256, 2)
gemm_sm(const bf16* __restrict__ Ah, const bf16* __restrict__ Al,
        const bf16* __restrict__ Bh, const bf16* __restrict__ Bl,
        const float* __restrict__ bias, const float* __restrict__ resid,
        float* __restrict__ Cf, int M, int N, int K) {
    extern __shared__ char sm[];
    const uint32_t sbase = smem_u32(sm);
    const int tid = threadIdx.x, lane = tid & 31, wid = tid >> 5;
    const int gr = lane >> 2, qc = lane & 3;
    const int warp_m = wid >> 1, warp_n = wid & 1;
    const int m0 = blockIdx.y * 128, n0 = blockIdx.x * 128;

    const int lp = tid >> 6, lr = tid & 63;
    const bf16* plane = (lp == 0) ? Ah : (lp == 1) ? Al : (lp == 2) ? Bh : Bl;
    const bool aP = lp < 2;
    int r0 = (aP ? m0 : n0) + lr;
    int r1 = r0 + 64;
    const uint32_t sz0 = (aP || r0 < N) ? 16u : 0u;
    const uint32_t sz1 = (aP || r1 < N) ? 16u : 0u;
    if (!aP) { if (r0 >= N) r0 = n0; if (r1 >= N) r1 = n0; }
    const char* src0 = (const char*)(plane + (size_t)r0 * K);
    const char* src1 = (const char*)(plane + (size_t)r1 * K);
    const uint32_t d0b = sbase + lp * PLANEB + lr * SROWB;
    const uint32_t d1b = d0b + 64 * SROWB;

    float c[2][8][4];
    #pragma unroll
    for (int mt = 0; mt < 2; mt++)
        #pragma unroll
        for (int nt = 0; nt < 8; nt++)
            #pragma unroll
            for (int r = 0; r < 4; r++) c[mt][nt][r] = 0.f;

    const int NK = K >> 5;

    #pragma unroll
    for (int cc2 = 0; cc2 < 4; cc2++) {
        CP_ASYNC16(d0b + cc2 * 16, src0 + cc2 * 16, sz0);
        CP_ASYNC16(d1b + cc2 * 16, src1 + cc2 * 16, sz1);
    }
    CP_COMMIT();

    for (int i = 0; i < NK; i++) {
        const int s = i & 1;
        CP_WAIT0();
        __syncthreads();
        if (i + 1 < NK) {
            const int kb = (i + 1) * 64;
            const uint32_t ds = (uint32_t)(s ^ 1) * STAGEB;
            #pragma unroll
            for (int cc2 = 0; cc2 < 4; cc2++) {
                CP_ASYNC16(d0b + ds + cc2 * 16, src0 + kb + cc2 * 16, sz0);
                CP_ASYNC16(d1b + ds + cc2 * 16, src1 + kb + cc2 * 16, sz1);
            }
            CP_COMMIT();
        }

        const char* st = sm + s * STAGEB;
        #pragma unroll
        for (int ks = 0; ks < 2; ks++) {
            uint32_t ah[2][4], al2[2][4], bh[8][2], bl2[8][2];
            #pragma unroll
            for (int mt = 0; mt < 2; mt++) {
                const int rb = warp_m * 32 + mt * 16 + gr;
                const char* p = st + rb * SROWB + ks * 32 + qc * 4;
                ah[mt][0] = *(const uint32_t*)(p);
                ah[mt][1] = *(const uint32_t*)(p + 8 * SROWB);
                ah[mt][2] = *(const uint32_t*)(p + 16);
                ah[mt][3] = *(const uint32_t*)(p + 8 * SROWB + 16);
                const char* q = p + PLANEB;
                al2[mt][0] = *(const uint32_t*)(q);
                al2[mt][1] = *(const uint32_t*)(q + 8 * SROWB);
                al2[mt][2] = *(const uint32_t*)(q + 16);
                al2[mt][3] = *(const uint32_t*)(q + 8 * SROWB + 16);
            }
            #pragma unroll
            for (int nt = 0; nt < 8; nt++) {
                const int cb = warp_n * 64 + nt * 8 + gr;
                const char* p = st + 2 * PLANEB + cb * SROWB + ks * 32 + qc * 4;
                bh[nt][0]  = *(const uint32_t*)(p);
                bh[nt][1]  = *(const uint32_t*)(p + 16);
                bl2[nt][0] = *(const uint32_t*)(p + PLANEB);
                bl2[nt][1] = *(const uint32_t*)(p + PLANEB + 16);
            }
            #pragma unroll
            for (int mt = 0; mt < 2; mt++)
                #pragma unroll
                for (int nt = 0; nt < 8; nt++)
                    mma_bf16(c[mt][nt], ah[mt][0], ah[mt][1], ah[mt][2], ah[mt][3],
                             bh[nt][0], bh[nt][1]);
            #pragma unroll
            for (int mt = 0; mt < 2; mt++)
                #pragma unroll
                for (int nt = 0; nt < 8; nt++)
                    mma_bf16(c[mt][nt], ah[mt][0], ah[mt][1], ah[mt][2], ah[mt][3],
                             bl2[nt][0], bl2[nt][1]);
            #pragma unroll
            for (int mt = 0; mt < 2; mt++)
                #pragma unroll
                for (int nt = 0; nt < 8; nt++)
                    mma_bf16(c[mt][nt], al2[mt][0], al2[mt][1], al2[mt][2], al2[mt][3],
                             bh[nt][0], bh[nt][1]);
        }
        // no trailing sync: next iteration's top barrier provides the ordering
    }

    const bool evenN = (N & 1) == 0;
    #pragma unroll
    for (int mt = 0; mt < 2; mt++) {
        #pragma unroll
        for (int nt = 0; nt < 8; nt++) {
            const int n = n0 + warp_n * 64 + nt * 8 + qc * 2;
            #pragma unroll
            for (int half = 0; half < 2; half++) {
                const int m = m0 + warp_m * 32 + mt * 16 + gr + half * 8;
                float v0 = c[mt][nt][half * 2 + 0];
                float v1 = c[mt][nt][half * 2 + 1];
                if (n + 1 < N) {
                    if (BIAS) { v0 += bias[n]; v1 += bias[n + 1]; }
                    if (RES) {
                        if (evenN) {
                            float2 r2 = *(const float2*)(resid + (size_t)m * N + n);
                            v0 += r2.x; v1 += r2.y;
                        } else {
                            v0 += resid[(size_t)m * N + n];
                            v1 += resid[(size_t)m * N + n + 1];
                        }
                    }
                    if (evenN) {
                        *(float2*)(Cf + (size_t)m * N + n) = make_float2(v0, v1);
                    } else {
                        Cf[(size_t)m * N + n] = v0;
                        Cf[(size_t)m * N + n + 1] = v1;
                    }
                } else if (n < N) {
                    if (BIAS) v0 += bias[n];
                    if (RES)  v0 += resid[(size_t)m * N + n];
                    Cf[(size_t)m * N + n] = v0;
                }
            }
        }
    }
}

// ---------------- conversion kernels (exactly 3 launches) --------------------
__device__ __forceinline__ uint32_t pack2(float x, float y) {
    bf16 hx = __float2bfloat16(x), hy = __float2bfloat16(y);
    return ((uint32_t)__bfloat16_as_ushort(hy) << 16) | __bfloat16_as_ushort(hx);
}
__device__ __forceinline__ void conv4(float4 v, uint2& h, uint2& l) {
    bf16 hx = __float2bfloat16(v.x), hy = __float2bfloat16(v.y);
    bf16 hz = __float2bfloat16(v.z), hw = __float2bfloat16(v.w);
    h.x = ((uint32_t)__bfloat16_as_ushort(hy) << 16) | __bfloat16_as_ushort(hx);
    h.y = ((uint32_t)__bfloat16_as_ushort(hw) << 16) | __bfloat16_as_ushort(hz);
    l.x = pack2(v.x - __bfloat162float(hx), v.y - __bfloat162float(hy));
    l.y = pack2(v.z - __bfloat162float(hz), v.w - __bfloat162float(hw));
}
__global__ void convert_qkv_all(const float* __restrict__ Wq, const float* __restrict__ Wk,
                                const float* __restrict__ Wv,
                                bf16* __restrict__ dh, bf16* __restrict__ dl) {
    const size_t seg4 = (size_t)CC * CC / 4;
    size_t i = (size_t)blockIdx.x * 256 + threadIdx.x;
    if (i < 3 * LL * seg4) {
        size_t l = i / (3 * seg4), r = i % (3 * seg4);
        int which = (int)(r / seg4);
        size_t rest = r % seg4;
        const float* src = (which == 0) ? Wq : (which == 1) ? Wk : Wv;
        uint2 h, lo;
        conv4(((const float4*)src)[l * seg4 + rest], h, lo);
        ((uint2*)dh)[i] = h;
        ((uint2*)dl)[i] = lo;
    }
}
__global__ void convert_rest(const float* __restrict__ Wo, const float* __restrict__ W1,
                             const float* __restrict__ W2,
                             bf16* __restrict__ woh, bf16* __restrict__ wol,
                             bf16* __restrict__ w1h, bf16* __restrict__ w1l,
                             bf16* __restrict__ w2h, bf16* __restrict__ w2l) {
    const size_t s0 = (size_t)LL * CC * CC / 4;
    const size_t s1 = (size_t)LL * FF * CC / 4;
    size_t i = (size_t)blockIdx.x * 256 + threadIdx.x;
    const float* src; bf16* dh; bf16* dl; size_t j;
    if (i < s0)           { src = Wo; dh = woh; dl = wol; j = i; }
    else if (i < s0 + s1) { src = W1; dh = w1h; dl = w1l; j = i - s0; }
    else if (i < s0 + 2*s1) { src = W2; dh = w2h; dl = w2l; j = i - s0 - s1; }
    else return;
    uint2 h, lo;
    conv4(((const float4*)src)[j], h, lo);
    ((uint2*)dh)[j] = h;
    ((uint2*)dl)[j] = lo;
}
__global__ void convert_head_bias(const float* __restrict__ head,
                                  bf16* __restrict__ whh, bf16* __restrict__ whl,
                                  const float* __restrict__ bq, const float* __restrict__ bk,
                                  const float* __restrict__ bv, float* __restrict__ bqkv) {
    const size_t n4 = (size_t)VV * CC / 4;
    size_t i = (size_t)blockIdx.x * 256 + threadIdx.x;
    if (i < n4) {
        uint2 h, lo;
        conv4(((const float4*)head)[i], h, lo);
        ((uint2*)whh)[i] = h;
        ((uint2*)whl)[i] = lo;
    }
    if (i < LL * 3 * CC) {
        int l = (int)(i / (3 * CC)), r = (int)(i % (3 * CC));
        float v = (r < CC) ? bq[l * CC + r]
                : (r < 2 * CC) ? bk[l * CC + r - CC]
                : bv[l * CC + r - 2 * CC];
        bqkv[i] = v;
    }
}

// ---------------- embedding --------------------------------------------------
__global__ void embed_kernel(const int* __restrict__ idx,
                             const float* __restrict__ tok,
                             const float* __restrict__ pos,
                             float* __restrict__ x) {
    int i = blockIdx.x * blockDim.x + threadIdx.x;
    if (i < BB * TT * CC) {
        int c = i % CC, bt = i / CC, t = bt % TT;
        x[i] = tok[(size_t)idx[bt] * CC + c] + pos[(size_t)t * CC + c];
    }
}

// ---------------- layernorm -> bf16 planes -----------------------------------
__global__ void ln_kernel(const float* __restrict__ in,
                          bf16* __restrict__ oh, bf16* __restrict__ ol,
                          const float* __restrict__ w, const float* __restrict__ b) {
    const int row = blockIdx.x, tid = threadIdx.x;
    const float4 x4 = *(const float4*)(in + (size_t)row * CC + tid * 4);
    __shared__ float red[256];
    red[tid] = x4.x + x4.y + x4.z + x4.w;
    __syncthreads();
    for (int o = 128; o > 0; o >>= 1) { if (tid < o) red[tid] += red[tid + o]; __syncthreads(); }
    const float mu = red[0] * (1.0f / CC);
    __syncthreads();
    const float d0 = x4.x - mu, d1 = x4.y - mu, d2 = x4.z - mu, d3 = x4.w - mu;
    red[tid] = d0 * d0 + d1 * d1 + d2 * d2 + d3 * d3;
    __syncthreads();
    for (int o = 128; o > 0; o >>= 1) { if (tid < o) red[tid] += red[tid + o]; __syncthreads(); }
    const float rstd = rsqrtf(red[0] * (1.0f / CC) + 1e-5f);
    const float4 w4 = *(const float4*)(w + tid * 4);
    const float4 b4 = *(const float4*)(b + tid * 4);
    float4 v;
    v.x = d0 * rstd * w4.x + b4.x;
    v.y = d1 * rstd * w4.y + b4.y;
    v.z = d2 * rstd * w4.z + b4.z;
    v.w = d3 * rstd * w4.w + b4.w;
    uint2 h, l;
    conv4(v, h, l);
    const size_t o4 = ((size_t)row * CC + tid * 4) >> 2;
    ((uint2*)oh)[o4] = h;
    ((uint2*)ol)[o4] = l;
}

// ---------------- attention: 8 q-rows per block, chunked K/V -----------------
#define QT 8
#define JCH 128
#define KVROW 68
#define ATTN_SMEM ((QT*KVROW + JCH*KVROW + QT*TT + 4*QT*DD + 8) * 4)

__global__ void __launch_bounds__(256)
attn_kernel(const float* __restrict__ qkv, bf16* __restrict__ yh, bf16* __restrict__ yl) {
    extern __shared__ float sf[];
    float* qs   = sf;
    float* kv   = sf + QT * KVROW;
    float* sc   = kv + JCH * KVROW;
    float* part = sc + QT * TT;
    float* invs = part + 4 * QT * DD;

    const int tid = threadIdx.x, lane = tid & 31, wid = tid >> 5;
    const int qb = blockIdx.x * QT;
    const int bh = blockIdx.y, b = bh / HH, h = bh % HH;
    const int RS = 3 * CC;
    const float* qp = qkv + (size_t)(b * TT) * RS + h * DD;
    const float* kp = qp + CC;
    const float* vp = qp + 2 * CC;
    const int lenmax = qb + QT;

    for (int i = tid; i < QT * 16; i += 256) {
        int r = i >> 4, d4 = i & 15;
        *(float4*)(qs + r * KVROW + 4 * d4) =
            *(const float4*)(qp + (size_t)(qb + r) * RS + 4 * d4);
    }

    for (int jt = 0; jt < lenmax; jt += JCH) {
        const int nr = min(JCH, lenmax - jt);
        __syncthreads();
        for (int i = tid; i < nr * 16; i += 256) {
            int r = i >> 4, d4 = i & 15;
            *(float4*)(kv + r * KVROW + 4 * d4) =
                *(const float4*)(kp + (size_t)(jt + r) * RS + 4 * d4);
        }
        __syncthreads();
        #pragma unroll
        for (int it = 0; it < 4; it++) {
            const int jj = (tid >> 3) + 32 * it;
            if (jj < nr) {
                const int r = tid & 7;
                const float* kr = kv + jj * KVROW;
                const float* qr = qs + r * KVROW;
                float dot = 0.f;
                #pragma unroll
                for (int d = 0; d < DD; d += 4) {
                    float4 kk = *(const float4*)(kr + d);
                    float4 qq = *(const float4*)(qr + d);
                    dot += kk.x * qq.x + kk.y * qq.y + kk.z * qq.z + kk.w * qq.w;
                }
                sc[r * TT + jt + jj] = dot * 0.125f;
            }
        }
    }
    __syncthreads();

    {
        const int r = wid;
        const int len = qb + r + 1;
        float mx = -1e30f;
        for (int j = lane; j < len; j += 32) mx = fmaxf(mx, sc[r * TT + j]);
        #pragma unroll
        for (int o = 16; o; o >>= 1) mx = fmaxf(mx, __shfl_xor_sync(~0u, mx, o));
        float sum = 0.f;
        for (int j = lane; j < len; j += 32) {
            float e = __expf(sc[r * TT + j] - mx);
            sc[r * TT + j] = e;
            sum += e;
        }
        #pragma unroll
        for (int o = 16; o; o >>= 1) sum += __shfl_xor_sync(~0u, sum, o);
        for (int j = len + lane; j < lenmax; j += 32) sc[r * TT + j] = 0.f;
        if (lane == 0) invs[r] = 1.0f / sum;
    }
    __syncthreads();

    const int g = tid >> 6;
    const int d = tid & 63;
    float acc[QT];
    #pragma unroll
    for (int r = 0; r < QT; r++) acc[r] = 0.f;

    for (int jt = 0; jt < lenmax; jt += JCH) {
        const int nr = min(JCH, lenmax - jt);
        __syncthreads();
        for (int i = tid; i < nr * 16; i += 256) {
            int r = i >> 4, d4 = i & 15;
            *(float4*)(kv + r * KVROW + 4 * d4) =
                *(const float4*)(vp + (size_t)(jt + r) * RS + 4 * d4);
        }
        __syncthreads();
        for (int jj = g; jj < nr; jj += 4) {
            const float vv = kv[jj * KVROW + d];
            const int j = jt + jj;
            #pragma unroll
            for (int r = 0; r < QT; r++)
                acc[r] = fmaf(sc[r * TT + j], vv, acc[r]);
        }
    }
    #pragma unroll
    for (int r = 0; r < QT; r++) part[(g * QT + r) * DD + d] = acc[r];
    __syncthreads();

    for (int i = tid; i < QT * DD; i += 256) {
        const int r = i >> 6, dd = i & 63;
        const float v = (part[(0 * QT + r) * DD + dd] + part[(1 * QT + r) * DD + dd] +
                         part[(2 * QT + r) * DD + dd] + part[(3 * QT + r) * DD + dd]) * invs[r];
        const size_t o = (size_t)(b * TT + qb + r) * CC + h * DD + dd;
        bf16 hh2, ll2; split2(v, hh2, ll2);
        yh[o] = hh2; yl[o] = ll2;
    }
}

// ---------------- host orchestration ---------------------------------------
static inline dim3 big_grid(int M, int N) {
    return dim3((N + 127) / 128, (M + 255) / 256);
}
static inline dim3 sm_grid(int M, int N) {
    return dim3((N + 127) / 128, (M + 127) / 128);
}

extern "C" void kernel_launch(void* const* d_in, const int* in_sizes, int n_in,
                              void* d_out, int out_size) {
    const int*   idx    = (const int*)  d_in[0];
    const float* tok    = (const float*)d_in[1];
    const float* pos    = (const float*)d_in[2];
    const float* ln1w   = (const float*)d_in[3];
    const float* ln1b   = (const float*)d_in[4];
    const float* Wq     = (const float*)d_in[5];
    const float* bq     = (const float*)d_in[6];
    const float* Wk     = (const float*)d_in[7];
    const float* bk     = (const float*)d_in[8];
    const float* Wv     = (const float*)d_in[9];
    const float* bv     = (const float*)d_in[10];
    const float* Wo     = (const float*)d_in[11];
    const float* bo     = (const float*)d_in[12];
    const float* ln2w   = (const float*)d_in[13];
    const float* ln2b   = (const float*)d_in[14];
    const float* W1     = (const float*)d_in[15];
    const float* b1     = (const float*)d_in[16];
    const float* W2     = (const float*)d_in[17];
    const float* b2     = (const float*)d_in[18];
    const float* lnfw   = (const float*)d_in[19];
    const float* lnfb   = (const float*)d_in[20];
    const float* head_w = (const float*)d_in[21];
    float* out = (float*)d_out;

    float *x, *qkv, *bqkv;
    bf16 *hh, *hl, *yh, *yl, *h2h, *h2l;
    bf16 *wqkvh, *wqkvl, *woh, *wol, *w1h, *w1l, *w2h, *w2l, *whh, *whl;
    cudaGetSymbolAddress((void**)&x,     g_x);
    cudaGetSymbolAddress((void**)&qkv,   g_qkv);
    cudaGetSymbolAddress((void**)&bqkv,  g_bqkv);
    cudaGetSymbolAddress((void**)&hh,    g_hh);
    cudaGetSymbolAddress((void**)&hl,    g_hl);
    cudaGetSymbolAddress((void**)&yh,    g_yh);
    cudaGetSymbolAddress((void**)&yl,    g_yl);
    cudaGetSymbolAddress((void**)&h2h,   g_h2h);
    cudaGetSymbolAddress((void**)&h2l,   g_h2l);
    cudaGetSymbolAddress((void**)&wqkvh, g_wqkvh);
    cudaGetSymbolAddress((void**)&wqkvl, g_wqkvl);
    cudaGetSymbolAddress((void**)&woh,   g_woh);
    cudaGetSymbolAddress((void**)&wol,   g_wol);
    cudaGetSymbolAddress((void**)&w1h,   g_w1h);
    cudaGetSymbolAddress((void**)&w1l,   g_w1l);
    cudaGetSymbolAddress((void**)&w2h,   g_w2h);
    cudaGetSymbolAddress((void**)&w2l,   g_w2l);
    cudaGetSymbolAddress((void**)&whh,   g_whh);
    cudaGetSymbolAddress((void**)&whl,   g_whl);

    cudaFuncSetAttribute(gemm_big<true,  false, false>, cudaFuncAttributeMaxDynamicSharedMemorySize, BIG_SMEM);
    cudaFuncSetAttribute(gemm_big<true,  true,  true >, cudaFuncAttributeMaxDynamicSharedMemorySize, BIG_SMEM);
    cudaFuncSetAttribute(gemm_big<false, false, false>, cudaFuncAttributeMaxDynamicSharedMemorySize, BIG_SMEM);
    cudaFuncSetAttribute(gemm_sm<true, true>,  cudaFuncAttributeMaxDynamicSharedMemorySize, SM_SMEM);
    cudaFuncSetAttribute(attn_kernel, cudaFuncAttributeMaxDynamicSharedMemorySize, ATTN_SMEM);

    const int M = BB * TT;

    {
        size_t seg4 = (size_t)CC * CC / 4;
        convert_qkv_all<<<(int)((3 * LL * seg4 + 255) / 256), 256>>>(Wq, Wk, Wv, wqkvh, wqkvl);
        size_t tot = (size_t)LL * CC * CC / 4 + 2 * ((size_t)LL * FF * CC / 4);
        convert_rest<<<(int)((tot + 255) / 256), 256>>>(Wo, W1, W2, woh, wol, w1h, w1l, w2h, w2l);
        size_t nh = (size_t)VV * CC / 4;
        convert_head_bias<<<(int)((nh + 255) / 256), 256>>>(head_w, whh, whl, bq, bk, bv, bqkv);
    }

    embed_kernel<<<(BB * TT * CC + 255) / 256, 256>>>(idx, tok, pos, x);

    for (int l = 0; l < LL; l++) {
        const size_t o3 = (size_t)l * 3 * CC * CC;
        const size_t o1 = (size_t)l * CC * CC;
        const size_t of = (size_t)l * FF * CC;

        ln_kernel<<<M, 256>>>(x, hh, hl, ln1w + (size_t)l * CC, ln1b + (size_t)l * CC);
        gemm_big<true, false, false><<<big_grid(M, 3 * CC), 256, BIG_SMEM>>>(
            hh, hl, wqkvh + o3, wqkvl + o3, bqkv + (size_t)l * 3 * CC,
            qkv, nullptr, nullptr, M, 3 * CC, CC);
        attn_kernel<<<dim3(TT / QT, BB * HH), 256, ATTN_SMEM>>>(qkv, yh, yl);
        gemm_sm<true, true><<<sm_grid(M, CC), 256, SM_SMEM>>>(
            yh, yl, woh + o1, wol + o1, bo + (size_t)l * CC, x, x, M, CC, CC);
        ln_kernel<<<M, 256>>>(x, hh, hl, ln2w + (size_t)l * CC, ln2b + (size_t)l * CC);
        gemm_big<true, true, true><<<big_grid(M, FF), 256, BIG_SMEM>>>(
            hh, hl, w1h + of, w1l + of, b1 + (size_t)l * FF,
            nullptr, h2h, h2l, M, FF, CC);
        gemm_sm<true, true><<<sm_grid(M, CC), 256, SM_SMEM>>>(
            h2h, h2l, w2h + of, w2l + of, b2 + (size_t)l * CC, x, x, M, CC, FF);
    }

    ln_kernel<<<M, 256>>>(x, hh, hl, lnfw, lnfb);
    gemm_big<false, false, false><<<big_grid(M, VV), 256, BIG_SMEM>>>(
        hh, hl, whh, whl, nullptr,
        out, nullptr, nullptr, M, VV, CC);
}

// round 17
// speedup vs baseline: 1.1683x; 1.0280x over previous
#include <cuda_runtime.h>
#include <cuda_bf16.h>
#include <math.h>
#include <stdint.h>

#define BB 2
#define TT 1024
#define CC 1024
#define HH 16
#define LL 4
#define VV 50257
#define DD 64
#define FF 4096

typedef __nv_bfloat16 bf16;

// ---------------- scratch (device globals) ----------------------------------
__device__ float g_x   [BB*TT*CC];
__device__ float g_qkv [BB*TT*3*CC];
__device__ float g_bqkv[LL*3*CC];
__device__ bf16  g_hh [BB*TT*CC],  g_hl [BB*TT*CC];
__device__ bf16  g_yh [BB*TT*CC],  g_yl [BB*TT*CC];
__device__ bf16  g_h2h[BB*TT*FF],  g_h2l[BB*TT*FF];
__device__ bf16  g_wqkvh[LL*3*CC*CC], g_wqkvl[LL*3*CC*CC];
__device__ bf16  g_woh[LL*CC*CC],     g_wol[LL*CC*CC];
__device__ bf16  g_w1h[LL*FF*CC],     g_w1l[LL*FF*CC];
__device__ bf16  g_w2h[LL*CC*FF],     g_w2l[LL*CC*FF];
__device__ bf16  g_whh[(size_t)VV*CC], g_whl[(size_t)VV*CC];

// ---------------- helpers ----------------------------------------------------
__device__ __forceinline__ uint32_t smem_u32(const void* p) {
    uint32_t a;
    asm("{ .reg .u64 t; cvta.to.shared.u64 t, %1; cvt.u32.u64 %0, t; }"
        : "=r"(a) : "l"(p));
    return a;
}
#define CP_ASYNC16(dst, src, sz) \
    asm volatile("cp.async.cg.shared.global [%0], [%1], 16, %2;" \
                 :: "r"(dst), "l"(src), "r"(sz) : "memory")
#define CP_COMMIT() asm volatile("cp.async.commit_group;" ::: "memory")
#define CP_WAIT1()  asm volatile("cp.async.wait_group 1;" ::: "memory")
#define CP_WAIT0()  asm volatile("cp.async.wait_group 0;" ::: "memory")

#define LDSM4(r0, r1, r2, r3, a) \
    asm volatile("ldmatrix.sync.aligned.m8n8.x4.shared.b16 {%0,%1,%2,%3}, [%4];" \
                 : "=r"(r0), "=r"(r1), "=r"(r2), "=r"(r3) : "r"(a))

// truncation split: hi = top 16 bits (exact LOP), lo = RN(x - hi)
__device__ __forceinline__ void split2(float x, bf16& h, bf16& l) {
    uint32_t hb = __float_as_uint(x) & 0xFFFF0000u;
    h = __ushort_as_bfloat16((unsigned short)(hb >> 16));
    l = __float2bfloat16(x - __uint_as_float(hb));
}
__device__ __forceinline__ float gelu_f(float v) {
    return 0.5f * v * (1.0f + erff(v * 0.70710678118654752f));
}
__device__ __forceinline__ uint32_t packbf(bf16 a, bf16 b) {
    return ((uint32_t)__bfloat16_as_ushort(b) << 16) | __bfloat16_as_ushort(a);
}
// vectorized truncation split of float4 -> packed hi/lo bf16x2 pairs
__device__ __forceinline__ void conv4(float4 v, uint2& h, uint2& l) {
    uint32_t hx = __float_as_uint(v.x) & 0xFFFF0000u;
    uint32_t hy = __float_as_uint(v.y) & 0xFFFF0000u;
    uint32_t hz = __float_as_uint(v.z) & 0xFFFF0000u;
    uint32_t hw = __float_as_uint(v.w) & 0xFFFF0000u;
    h.x = (hx >> 16) | hy;
    h.y = (hz >> 16) | hw;
    __nv_bfloat162 p0 = __floats2bfloat162_rn(v.x - __uint_as_float(hx),
                                              v.y - __uint_as_float(hy));
    __nv_bfloat162 p1 = __floats2bfloat162_rn(v.z - __uint_as_float(hz),
                                              v.w - __uint_as_float(hw));
    l.x = *reinterpret_cast<uint32_t*>(&p0);
    l.y = *reinterpret_cast<uint32_t*>(&p1);
}

__device__ __forceinline__ void mma_bf16(float* c,
        uint32_t a0, uint32_t a1, uint32_t a2, uint32_t a3,
        uint32_t b0, uint32_t b1) {
    asm volatile("mma.sync.aligned.m16n8k16.row.col.f32.bf16.bf16.f32 "
                 "{%0,%1,%2,%3}, {%4,%5,%6,%7}, {%8,%9}, {%0,%1,%2,%3};"
                 : "+f"(c[0]), "+f"(c[1]), "+f"(c[2]), "+f"(c[3])
                 : "r"(a0), "r"(a1), "r"(a2), "r"(a3), "r"(b0), "r"(b1));
}

// ============================================================================
// gemm_big: 256x128 CTA tile, 8 warps (4m x 2n), warp 64x64, 1 CTA/SM.
// ldmatrix fragments, BK=32, 3-stage cp.async pipeline.
// ============================================================================
#define BPLANE 10240
#define APLANE 20480
#define BIG_STAGE (2*APLANE + 2*BPLANE)
#define BIG_SMEM (3*BIG_STAGE)

template<bool BIAS, bool GELU_, bool POUT>
__global__ void __launch_bounds__(256, 1)
gemm_big(const bf16* __restrict__ Ah, const bf16* __restrict__ Al,
         const bf16* __restrict__ Bh, const bf16* __restrict__ Bl,
         const float* __restrict__ bias,
         float* __restrict__ Cf, bf16* __restrict__ Ch, bf16* __restrict__ Cl,
         int M, int N, int K) {
    extern __shared__ char sm[];
    const uint32_t sbase = smem_u32(sm);
    const int tid = threadIdx.x, lane = tid & 31, wid = tid >> 5;
    const int gr = lane >> 2, qc = lane & 3;
    const int warp_m = wid >> 1, warp_n = wid & 1;
    const int m0 = blockIdx.y * 256, n0 = blockIdx.x * 128;

    const int lrw = tid >> 2, lsg = tid & 3;
    const size_t rowB = (size_t)K * 2;
    const char* aRow0  = (const char*)Ah + (size_t)(m0 + lrw) * rowB + lsg * 16;
    const char* alRow0 = (const char*)Al + (size_t)(m0 + lrw) * rowB + lsg * 16;
    const char* bSrc[2]; const char* blSrc[2]; uint32_t bsz[2];
    #pragma unroll
    for (int j = 0; j < 2; j++) {
        int nrow = n0 + lrw + 64 * j;
        bsz[j] = (nrow < N) ? 16u : 0u;
        if (nrow >= N) nrow = n0;
        bSrc[j]  = (const char*)Bh + (size_t)nrow * rowB + lsg * 16;
        blSrc[j] = (const char*)Bl + (size_t)nrow * rowB + lsg * 16;
    }
    const uint32_t aDst0 = sbase + lrw * 80 + lsg * 16;
    const uint32_t bDst0 = sbase + 2 * APLANE + lrw * 80 + lsg * 16;

    const int laneRow = lane & 15;
    const uint32_t khalf = (uint32_t)(lane >> 4) * 16;
    uint32_t baseA[4], baseB[4];
    #pragma unroll
    for (int mt = 0; mt < 4; mt++)
        baseA[mt] = sbase + (uint32_t)(warp_m * 64 + mt * 16 + laneRow) * 80 + khalf;
    #pragma unroll
    for (int g2 = 0; g2 < 4; g2++)
        baseB[g2] = sbase + 2 * APLANE +
                    (uint32_t)(warp_n * 64 + g2 * 16 + laneRow) * 80 + khalf;

    float c[4][8][4];
    #pragma unroll
    for (int mt = 0; mt < 4; mt++)
        #pragma unroll
        for (int nt = 0; nt < 8; nt++)
            #pragma unroll
            for (int r = 0; r < 4; r++) c[mt][nt][r] = 0.f;

    const int NK = K >> 5;

    #pragma unroll
    for (int pc = 0; pc < 2; pc++) {
        const size_t kb = (size_t)pc * 64;
        const uint32_t ds = (uint32_t)pc * BIG_STAGE;
        #pragma unroll
        for (int j = 0; j < 4; j++) {
            const size_t so = (size_t)(64 * j) * rowB + kb;
            CP_ASYNC16(aDst0 + ds + j * 5120,          aRow0 + so, 16u);
            CP_ASYNC16(aDst0 + ds + APLANE + j * 5120, alRow0 + so, 16u);
        }
        #pragma unroll
        for (int j = 0; j < 2; j++) {
            CP_ASYNC16(bDst0 + ds + j * 5120,          bSrc[j] + kb,  bsz[j]);
            CP_ASYNC16(bDst0 + ds + BPLANE + j * 5120, blSrc[j] + kb, bsz[j]);
        }
        CP_COMMIT();
    }

    int s = 0;
    for (int i = 0; i < NK; i++) {
        if (i + 1 < NK) { CP_WAIT1(); } else { CP_WAIT0(); }
        __syncthreads();
        if (i + 2 < NK) {
            const size_t kb = (size_t)(i + 2) * 64;
            int sn = s + 2; if (sn >= 3) sn -= 3;
            const uint32_t ds = (uint32_t)sn * BIG_STAGE;
            #pragma unroll
            for (int j = 0; j < 4; j++) {
                const size_t so = (size_t)(64 * j) * rowB + kb;
                CP_ASYNC16(aDst0 + ds + j * 5120,          aRow0 + so, 16u);
                CP_ASYNC16(aDst0 + ds + APLANE + j * 5120, alRow0 + so, 16u);
            }
            #pragma unroll
            for (int j = 0; j < 2; j++) {
                CP_ASYNC16(bDst0 + ds + j * 5120,          bSrc[j] + kb,  bsz[j]);
                CP_ASYNC16(bDst0 + ds + BPLANE + j * 5120, blSrc[j] + kb, bsz[j]);
            }
            CP_COMMIT();
        }

        const uint32_t so = (uint32_t)s * BIG_STAGE;
        #pragma unroll
        for (int ks = 0; ks < 2; ks++) {
            const uint32_t ko = so + ks * 32;
            uint32_t ah[4][4], al2[4][4], bh[8][2], bl2[8][2];
            #pragma unroll
            for (int mt = 0; mt < 4; mt++) {
                LDSM4(ah[mt][0], ah[mt][1], ah[mt][2], ah[mt][3], baseA[mt] + ko);
                LDSM4(al2[mt][0], al2[mt][1], al2[mt][2], al2[mt][3],
                      baseA[mt] + ko + APLANE);
            }
            #pragma unroll
            for (int g2 = 0; g2 < 4; g2++) {
                uint32_t t0, t1, t2, t3;
                LDSM4(t0, t1, t2, t3, baseB[g2] + ko);
                bh[2*g2][0] = t0; bh[2*g2+1][0] = t1;
                bh[2*g2][1] = t2; bh[2*g2+1][1] = t3;
                LDSM4(t0, t1, t2, t3, baseB[g2] + ko + BPLANE);
                bl2[2*g2][0] = t0; bl2[2*g2+1][0] = t1;
                bl2[2*g2][1] = t2; bl2[2*g2+1][1] = t3;
            }
            #pragma unroll
            for (int mt = 0; mt < 4; mt++)
                #pragma unroll
                for (int nt = 0; nt < 8; nt++)
                    mma_bf16(c[mt][nt], ah[mt][0], ah[mt][1], ah[mt][2], ah[mt][3],
                             bh[nt][0], bh[nt][1]);
            #pragma unroll
            for (int mt = 0; mt < 4; mt++)
                #pragma unroll
                for (int nt = 0; nt < 8; nt++)
                    mma_bf16(c[mt][nt], ah[mt][0], ah[mt][1], ah[mt][2], ah[mt][3],
                             bl2[nt][0], bl2[nt][1]);
            #pragma unroll
            for (int mt = 0; mt < 4; mt++)
                #pragma unroll
                for (int nt = 0; nt < 8; nt++)
                    mma_bf16(c[mt][nt], al2[mt][0], al2[mt][1], al2[mt][2], al2[mt][3],
                             bh[nt][0], bh[nt][1]);
        }
        s++; if (s == 3) s = 0;
    }

    const bool evenN = (N & 1) == 0;
    #pragma unroll
    for (int mt = 0; mt < 4; mt++) {
        #pragma unroll
        for (int nt = 0; nt < 8; nt++) {
            const int n = n0 + warp_n * 64 + nt * 8 + qc * 2;
            #pragma unroll
            for (int half = 0; half < 2; half++) {
                const int m = m0 + warp_m * 64 + mt * 16 + gr + half * 8;
                float v0 = c[mt][nt][half * 2 + 0];
                float v1 = c[mt][nt][half * 2 + 1];
                if (n + 1 < N) {
                    if (BIAS)  { v0 += bias[n]; v1 += bias[n + 1]; }
                    if (GELU_) { v0 = gelu_f(v0); v1 = gelu_f(v1); }
                    if (POUT) {
                        bf16 h0, l0, h1, l1;
                        split2(v0, h0, l0); split2(v1, h1, l1);
                        *(uint32_t*)(Ch + (size_t)m * N + n) = packbf(h0, h1);
                        *(uint32_t*)(Cl + (size_t)m * N + n) = packbf(l0, l1);
                    } else if (evenN) {
                        *(float2*)(Cf + (size_t)m * N + n) = make_float2(v0, v1);
                    } else {
                        Cf[(size_t)m * N + n] = v0;
                        Cf[(size_t)m * N + n + 1] = v1;
                    }
                } else if (n < N) {
                    if (BIAS)  v0 += bias[n];
                    if (GELU_) v0 = gelu_f(v0);
                    if (POUT) {
                        bf16 h0, l0; split2(v0, h0, l0);
                        Ch[(size_t)m * N + n] = h0;
                        Cl[(size_t)m * N + n] = l0;
                    } else {
                        Cf[(size_t)m * N + n] = v0;
                    }
                }
            }
        }
    }
}

// ============================================================================
// gemm_sm: 128x128 tile, warp 32x64, 2 CTA/SM, scalar LDS fragments
// ============================================================================
#define SROWB  80
#define PLANEB 10240
#define STAGEB 40960
#define SM_SMEM (2*STAGEB)

template<bool BIAS, bool RES>
__global__ void __launch_bounds__(256, 2)
gemm_sm(const bf16* __restrict__ Ah, const bf16* __restrict__ Al,
        const bf16* __restrict__ Bh, const bf16* __restrict__ Bl,
        const float* __restrict__ bias, const float* __restrict__ resid,
        float* __restrict__ Cf, int M, int N, int K) {
    extern __shared__ char sm[];
    const uint32_t sbase = smem_u32(sm);
    const int tid = threadIdx.x, lane = tid & 31, wid = tid >> 5;
    const int gr = lane >> 2, qc = lane & 3;
    const int warp_m = wid >> 1, warp_n = wid & 1;
    const int m0 = blockIdx.y * 128, n0 = blockIdx.x * 128;

    const int lp = tid >> 6, lr = tid & 63;
    const bf16* plane = (lp == 0) ? Ah : (lp == 1) ? Al : (lp == 2) ? Bh : Bl;
    const bool aP = lp < 2;
    int r0 = (aP ? m0 : n0) + lr;
    int r1 = r0 + 64;
    const uint32_t sz0 = (aP || r0 < N) ? 16u : 0u;
    const uint32_t sz1 = (aP || r1 < N) ? 16u : 0u;
    if (!aP) { if (r0 >= N) r0 = n0; if (r1 >= N) r1 = n0; }
    const char* src0 = (const char*)(plane + (size_t)r0 * K);
    const char* src1 = (const char*)(plane + (size_t)r1 * K);
    const uint32_t d0b = sbase + lp * PLANEB + lr * SROWB;
    const uint32_t d1b = d0b + 64 * SROWB;

    float c[2][8][4];
    #pragma unroll
    for (int mt = 0; mt < 2; mt++)
        #pragma unroll
        for (int nt = 0; nt < 8; nt++)
            #pragma unroll
            for (int r = 0; r < 4; r++) c[mt][nt][r] = 0.f;

    const int NK = K >> 5;

    #pragma unroll
    for (int cc2 = 0; cc2 < 4; cc2++) {
        CP_ASYNC16(d0b + cc2 * 16, src0 + cc2 * 16, sz0);
        CP_ASYNC16(d1b + cc2 * 16, src1 + cc2 * 16, sz1);
    }
    CP_COMMIT();

    for (int i = 0; i < NK; i++) {
        const int s = i & 1;
        CP_WAIT0();
        __syncthreads();
        if (i + 1 < NK) {
            const int kb = (i + 1) * 64;
            const uint32_t ds = (uint32_t)(s ^ 1) * STAGEB;
            #pragma unroll
            for (int cc2 = 0; cc2 < 4; cc2++) {
                CP_ASYNC16(d0b + ds + cc2 * 16, src0 + kb + cc2 * 16, sz0);
                CP_ASYNC16(d1b + ds + cc2 * 16, src1 + kb + cc2 * 16, sz1);
            }
            CP_COMMIT();
        }

        const char* st = sm + s * STAGEB;
        #pragma unroll
        for (int ks = 0; ks < 2; ks++) {
            uint32_t ah[2][4], al2[2][4], bh[8][2], bl2[8][2];
            #pragma unroll
            for (int mt = 0; mt < 2; mt++) {
                const int rb = warp_m * 32 + mt * 16 + gr;
                const char* p = st + rb * SROWB + ks * 32 + qc * 4;
                ah[mt][0] = *(const uint32_t*)(p);
                ah[mt][1] = *(const uint32_t*)(p + 8 * SROWB);
                ah[mt][2] = *(const uint32_t*)(p + 16);
                ah[mt][3] = *(const uint32_t*)(p + 8 * SROWB + 16);
                const char* q = p + PLANEB;
                al2[mt][0] = *(const uint32_t*)(q);
                al2[mt][1] = *(const uint32_t*)(q + 8 * SROWB);
                al2[mt][2] = *(const uint32_t*)(q + 16);
                al2[mt][3] = *(const uint32_t*)(q + 8 * SROWB + 16);
            }
            #pragma unroll
            for (int nt = 0; nt < 8; nt++) {
                const int cb = warp_n * 64 + nt * 8 + gr;
                const char* p = st + 2 * PLANEB + cb * SROWB + ks * 32 + qc * 4;
                bh[nt][0]  = *(const uint32_t*)(p);
                bh[nt][1]  = *(const uint32_t*)(p + 16);
                bl2[nt][0] = *(const uint32_t*)(p + PLANEB);
                bl2[nt][1] = *(const uint32_t*)(p + PLANEB + 16);
            }
            #pragma unroll
            for (int mt = 0; mt < 2; mt++)
                #pragma unroll
                for (int nt = 0; nt < 8; nt++)
                    mma_bf16(c[mt][nt], ah[mt][0], ah[mt][1], ah[mt][2], ah[mt][3],
                             bh[nt][0], bh[nt][1]);
            #pragma unroll
            for (int mt = 0; mt < 2; mt++)
                #pragma unroll
                for (int nt = 0; nt < 8; nt++)
                    mma_bf16(c[mt][nt], ah[mt][0], ah[mt][1], ah[mt][2], ah[mt][3],
                             bl2[nt][0], bl2[nt][1]);
            #pragma unroll
            for (int mt = 0; mt < 2; mt++)
                #pragma unroll
                for (int nt = 0; nt < 8; nt++)
                    mma_bf16(c[mt][nt], al2[mt][0], al2[mt][1], al2[mt][2], al2[mt][3],
                             bh[nt][0], bh[nt][1]);
        }
    }

    const bool evenN = (N & 1) == 0;
    #pragma unroll
    for (int mt = 0; mt < 2; mt++) {
        #pragma unroll
        for (int nt = 0; nt < 8; nt++) {
            const int n = n0 + warp_n * 64 + nt * 8 + qc * 2;
            #pragma unroll
            for (int half = 0; half < 2; half++) {
                const int m = m0 + warp_m * 32 + mt * 16 + gr + half * 8;
                float v0 = c[mt][nt][half * 2 + 0];
                float v1 = c[mt][nt][half * 2 + 1];
                if (n + 1 < N) {
                    if (BIAS) { v0 += bias[n]; v1 += bias[n + 1]; }
                    if (RES) {
                        if (evenN) {
                            float2 r2 = *(const float2*)(resid + (size_t)m * N + n);
                            v0 += r2.x; v1 += r2.y;
                        } else {
                            v0 += resid[(size_t)m * N + n];
                            v1 += resid[(size_t)m * N + n + 1];
                        }
                    }
                    if (evenN) {
                        *(float2*)(Cf + (size_t)m * N + n) = make_float2(v0, v1);
                    } else {
                        Cf[(size_t)m * N + n] = v0;
                        Cf[(size_t)m * N + n + 1] = v1;
                    }
                } else if (n < N) {
                    if (BIAS) v0 += bias[n];
                    if (RES)  v0 += resid[(size_t)m * N + n];
                    Cf[(size_t)m * N + n] = v0;
                }
            }
        }
    }
}

// ---------------- fused weight conversion (ONE launch) -----------------------
__global__ void convert_all(
    const float* __restrict__ Wq, const float* __restrict__ Wk,
    const float* __restrict__ Wv, const float* __restrict__ Wo,
    const float* __restrict__ W1, const float* __restrict__ W2,
    const float* __restrict__ head,
    const float* __restrict__ bq, const float* __restrict__ bk,
    const float* __restrict__ bv,
    bf16* __restrict__ wqkvh, bf16* __restrict__ wqkvl,
    bf16* __restrict__ woh, bf16* __restrict__ wol,
    bf16* __restrict__ w1h, bf16* __restrict__ w1l,
    bf16* __restrict__ w2h, bf16* __restrict__ w2l,
    bf16* __restrict__ whh, bf16* __restrict__ whl,
    float* __restrict__ bqkv) {
    const size_t seg4 = (size_t)CC * CC / 4;
    const size_t t0 = 3 * LL * seg4;
    const size_t t1 = t0 + LL * seg4;
    const size_t sW = (size_t)LL * FF * CC / 4;
    const size_t t2 = t1 + sW;
    const size_t t3 = t2 + sW;
    const size_t t4 = t3 + (size_t)VV * CC / 4;
    size_t i = (size_t)blockIdx.x * 256 + threadIdx.x;
    if (i < t0) {
        size_t l = i / (3 * seg4), r = i % (3 * seg4);
        int w = (int)(r / seg4); size_t rest = r % seg4;
        const float* src = (w == 0) ? Wq : (w == 1) ? Wk : Wv;
        uint2 h, lo; conv4(((const float4*)src)[l * seg4 + rest], h, lo);
        ((uint2*)wqkvh)[i] = h; ((uint2*)wqkvl)[i] = lo;
    } else if (i < t1) {
        size_t j = i - t0;
        uint2 h, lo; conv4(((const float4*)Wo)[j], h, lo);
        ((uint2*)woh)[j] = h; ((uint2*)wol)[j] = lo;
    } else if (i < t2) {
        size_t j = i - t1;
        uint2 h, lo; conv4(((const float4*)W1)[j], h, lo);
        ((uint2*)w1h)[j] = h; ((uint2*)w1l)[j] = lo;
    } else if (i < t3) {
        size_t j = i - t2;
        uint2 h, lo; conv4(((const float4*)W2)[j], h, lo);
        ((uint2*)w2h)[j] = h; ((uint2*)w2l)[j] = lo;
    } else if (i < t4) {
        size_t j = i - t3;
        uint2 h, lo; conv4(((const float4*)head)[j], h, lo);
        ((uint2*)whh)[j] = h; ((uint2*)whl)[j] = lo;
    } else if (i < t4 + LL * 3 * CC) {
        size_t j = i - t4;
        int l = (int)(j / (3 * CC)), r = (int)(j % (3 * CC));
        float v = (r < CC) ? bq[l * CC + r]
                : (r < 2 * CC) ? bk[l * CC + r - CC]
                : bv[l * CC + r - 2 * CC];
        bqkv[j] = v;
    }
}

// ---------------- embedding --------------------------------------------------
__global__ void embed_kernel(const int* __restrict__ idx,
                             const float* __restrict__ tok,
                             const float* __restrict__ pos,
                             float* __restrict__ x) {
    int i = blockIdx.x * blockDim.x + threadIdx.x;
    if (i < BB * TT * CC) {
        int c = i % CC, bt = i / CC, t = bt % TT;
        x[i] = tok[(size_t)idx[bt] * CC + c] + pos[(size_t)t * CC + c];
    }
}

// ---------------- layernorm -> bf16 planes -----------------------------------
__global__ void ln_kernel(const float* __restrict__ in,
                          bf16* __restrict__ oh, bf16* __restrict__ ol,
                          const float* __restrict__ w, const float* __restrict__ b) {
    const int row = blockIdx.x, tid = threadIdx.x;
    const float4 x4 = *(const float4*)(in + (size_t)row * CC + tid * 4);
    __shared__ float red[256];
    red[tid] = x4.x + x4.y + x4.z + x4.w;
    __syncthreads();
    for (int o = 128; o > 0; o >>= 1) { if (tid < o) red[tid] += red[tid + o]; __syncthreads(); }
    const float mu = red[0] * (1.0f / CC);
    __syncthreads();
    const float d0 = x4.x - mu, d1 = x4.y - mu, d2 = x4.z - mu, d3 = x4.w - mu;
    red[tid] = d0 * d0 + d1 * d1 + d2 * d2 + d3 * d3;
    __syncthreads();
    for (int o = 128; o > 0; o >>= 1) { if (tid < o) red[tid] += red[tid + o]; __syncthreads(); }
    const float rstd = rsqrtf(red[0] * (1.0f / CC) + 1e-5f);
    const float4 w4 = *(const float4*)(w + tid * 4);
    const float4 b4 = *(const float4*)(b + tid * 4);
    float4 v;
    v.x = d0 * rstd * w4.x + b4.x;
    v.y = d1 * rstd * w4.y + b4.y;
    v.z = d2 * rstd * w4.z + b4.z;
    v.w = d3 * rstd * w4.w + b4.w;
    uint2 h, l;
    conv4(v, h, l);
    const size_t o4 = ((size_t)row * CC + tid * 4) >> 2;
    ((uint2*)oh)[o4] = h;
    ((uint2*)ol)[o4] = l;
}

// ---------------- attention: 16 q-rows/block, double-buffered cp.async -------
#define QT 16
#define JCH 128
#define KVROW 68
#define KVBUF (JCH*KVROW)
#define ATTN_SMEM ((QT*KVROW + 2*KVBUF + QT*TT + 8*QT*DD + QT) * 4)

__global__ void __launch_bounds__(256)
attn_kernel(const float* __restrict__ qkv, bf16* __restrict__ yh, bf16* __restrict__ yl) {
    extern __shared__ float sf[];
    float* qs   = sf;                       // QT*KVROW
    float* kvb  = sf + QT * KVROW;          // 2*KVBUF
    float* sc   = kvb + 2 * KVBUF;          // QT*TT
    float* part = sc + QT * TT;             // 8*QT*DD
    float* invs = part + 8 * QT * DD;       // QT

    const int tid = threadIdx.x, lane = tid & 31, wid = tid >> 5;
    const int qb = blockIdx.x * QT;
    const int bh = blockIdx.y, b = bh / HH, h = bh % HH;
    const int RS = 3 * CC;
    const float* qp = qkv + (size_t)(b * TT) * RS + h * DD;
    const float* kp = qp + CC;
    const float* vp = qp + 2 * CC;
    const int lenmax = qb + QT;
    const int nch = (lenmax + JCH - 1) / JCH;
    const uint32_t kvb_u = smem_u32(kvb);

    // q load: exactly 256 float4
    {
        int r = tid >> 4, d4 = tid & 15;
        *(float4*)(qs + r * KVROW + 4 * d4) =
            *(const float4*)(qp + (size_t)(qb + r) * RS + 4 * d4);
    }

    // ---- K phase (double-buffered) ----
    {
        int nr0 = min(JCH, lenmax);
        for (int i = tid; i < nr0 * 16; i += 256) {
            int r = i >> 4, s4 = i & 15;
            CP_ASYNC16(kvb_u + (r * KVROW + 4 * s4) * 4,
                       kp + (size_t)r * RS + 4 * s4, 16u);
        }
        CP_COMMIT();
    }
    for (int ci = 0; ci < nch; ci++) {
        const int jt = ci * JCH;
        const int nr = min(JCH, lenmax - jt);
        __syncthreads();                 // prev compute done (and q stores visible)
        if (ci + 1 < nch) {
            const int jt2 = jt + JCH;
            const int nr2 = min(JCH, lenmax - jt2);
            const uint32_t bo = (uint32_t)((ci + 1) & 1) * (KVBUF * 4);
            for (int i = tid; i < nr2 * 16; i += 256) {
                int r = i >> 4, s4 = i & 15;
                CP_ASYNC16(kvb_u + bo + (r * KVROW + 4 * s4) * 4,
                           kp + (size_t)(jt2 + r) * RS + 4 * s4, 16u);
            }
            CP_COMMIT();
            CP_WAIT1();
        } else {
            CP_WAIT0();
        }
        __syncthreads();
        const float* kb = kvb + (ci & 1) * KVBUF;
        const int r = tid & 15;
        const float* qr = qs + r * KVROW;
        #pragma unroll
        for (int it = 0; it < 8; it++) {
            const int jj = (tid >> 4) + 16 * it;
            if (jj < nr) {
                const float* kr = kb + jj * KVROW;
                float dot = 0.f;
                #pragma unroll
                for (int d = 0; d < DD; d += 4) {
                    float4 kk = *(const float4*)(kr + d);
                    float4 qq = *(const float4*)(qr + d);
                    dot += kk.x * qq.x + kk.y * qq.y + kk.z * qq.z + kk.w * qq.w;
                }
                sc[r * TT + jt + jj] = dot * 0.125f;
            }
        }
    }
    __syncthreads();

    // overlap: start V chunk 0 load during softmax
    {
        int nr0 = min(JCH, lenmax);
        for (int i = tid; i < nr0 * 16; i += 256) {
            int r = i >> 4, s4 = i & 15;
            CP_ASYNC16(kvb_u + (r * KVROW + 4 * s4) * 4,
                       vp + (size_t)r * RS + 4 * s4, 16u);
        }
        CP_COMMIT();
    }

    // softmax: warp wid owns rows 2wid, 2wid+1
    #pragma unroll
    for (int rr = 0; rr < 2; rr++) {
        const int r = wid * 2 + rr;
        const int len = qb + r + 1;
        float mx = -1e30f;
        for (int j = lane; j < len; j += 32) mx = fmaxf(mx, sc[r * TT + j]);
        #pragma unroll
        for (int o = 16; o; o >>= 1) mx = fmaxf(mx, __shfl_xor_sync(~0u, mx, o));
        float sum = 0.f;
        for (int j = lane; j < len; j += 32) {
            float e = __expf(sc[r * TT + j] - mx);
            sc[r * TT + j] = e;
            sum += e;
        }
        #pragma unroll
        for (int o = 16; o; o >>= 1) sum += __shfl_xor_sync(~0u, sum, o);
        for (int j = len + lane; j < lenmax; j += 32) sc[r * TT + j] = 0.f;
        if (lane == 0) invs[r] = 1.0f / sum;
    }

    // ---- V phase (double-buffered) ----
    const int g = tid >> 5;          // 0..7
    const int d2 = lane * 2;         // 0..62
    float2 acc[QT];
    #pragma unroll
    for (int r = 0; r < QT; r++) acc[r] = make_float2(0.f, 0.f);

    for (int ci = 0; ci < nch; ci++) {
        const int jt = ci * JCH;
        const int nr = min(JCH, lenmax - jt);
        __syncthreads();
        if (ci + 1 < nch) {
            const int jt2 = jt + JCH;
            const int nr2 = min(JCH, lenmax - jt2);
            const uint32_t bo = (uint32_t)((ci + 1) & 1) * (KVBUF * 4);
            for (int i = tid; i < nr2 * 16; i += 256) {
                int r = i >> 4, s4 = i & 15;
                CP_ASYNC16(kvb_u + bo + (r * KVROW + 4 * s4) * 4,
                           vp + (size_t)(jt2 + r) * RS + 4 * s4, 16u);
            }
            CP_COMMIT();
            CP_WAIT1();
        } else {
            CP_WAIT0();
        }
        __syncthreads();
        const float* vb = kvb + (ci & 1) * KVBUF;
        for (int jj = g; jj < nr; jj += 8) {
            const float2 vv = *(const float2*)(vb + jj * KVROW + d2);
            const int j = jt + jj;
            #pragma unroll
            for (int r = 0; r < QT; r++) {
                const float p = sc[r * TT + j];
                acc[r].x = fmaf(p, vv.x, acc[r].x);
                acc[r].y = fmaf(p, vv.y, acc[r].y);
            }
        }
    }
    #pragma unroll
    for (int r = 0; r < QT; r++) {
        part[(g * QT + r) * DD + d2]     = acc[r].x;
        part[(g * QT + r) * DD + d2 + 1] = acc[r].y;
    }
    __syncthreads();

    for (int i = tid; i < QT * DD; i += 256) {
        const int r = i >> 6, dd = i & 63;
        float v = 0.f;
        #pragma unroll
        for (int gg = 0; gg < 8; gg++) v += part[(gg * QT + r) * DD + dd];
        v *= invs[r];
        const size_t o = (size_t)(b * TT + qb + r) * CC + h * DD + dd;
        bf16 hh2, ll2; split2(v, hh2, ll2);
        yh[o] = hh2; yl[o] = ll2;
    }
}

// ---------------- host orchestration ---------------------------------------
static inline dim3 big_grid(int M, int N) {
    return dim3((N + 127) / 128, (M + 255) / 256);
}
static inline dim3 sm_grid(int M, int N) {
    return dim3((N + 127) / 128, (M + 127) / 128);
}

extern "C" void kernel_launch(void* const* d_in, const int* in_sizes, int n_in,
                              void* d_out, int out_size) {
    const int*   idx    = (const int*)  d_in[0];
    const float* tok    = (const float*)d_in[1];
    const float* pos    = (const float*)d_in[2];
    const float* ln1w   = (const float*)d_in[3];
    const float* ln1b   = (const float*)d_in[4];
    const float* Wq     = (const float*)d_in[5];
    const float* bq     = (const float*)d_in[6];
    const float* Wk     = (const float*)d_in[7];
    const float* bk     = (const float*)d_in[8];
    const float* Wv     = (const float*)d_in[9];
    const float* bv     = (const float*)d_in[10];
    const float* Wo     = (const float*)d_in[11];
    const float* bo     = (const float*)d_in[12];
    const float* ln2w   = (const float*)d_in[13];
    const float* ln2b   = (const float*)d_in[14];
    const float* W1     = (const float*)d_in[15];
    const float* b1     = (const float*)d_in[16];
    const float* W2     = (const float*)d_in[17];
    const float* b2     = (const float*)d_in[18];
    const float* lnfw   = (const float*)d_in[19];
    const float* lnfb   = (const float*)d_in[20];
    const float* head_w = (const float*)d_in[21];
    float* out = (float*)d_out;

    float *x, *qkv, *bqkv;
    bf16 *hh, *hl, *yh, *yl, *h2h, *h2l;
    bf16 *wqkvh, *wqkvl, *woh, *wol, *w1h, *w1l, *w2h, *w2l, *whh, *whl;
    cudaGetSymbolAddress((void**)&x,     g_x);
    cudaGetSymbolAddress((void**)&qkv,   g_qkv);
    cudaGetSymbolAddress((void**)&bqkv,  g_bqkv);
    cudaGetSymbolAddress((void**)&hh,    g_hh);
    cudaGetSymbolAddress((void**)&hl,    g_hl);
    cudaGetSymbolAddress((void**)&yh,    g_yh);
    cudaGetSymbolAddress((void**)&yl,    g_yl);
    cudaGetSymbolAddress((void**)&h2h,   g_h2h);
    cudaGetSymbolAddress((void**)&h2l,   g_h2l);
    cudaGetSymbolAddress((void**)&wqkvh, g_wqkvh);
    cudaGetSymbolAddress((void**)&wqkvl, g_wqkvl);
    cudaGetSymbolAddress((void**)&woh,   g_woh);
    cudaGetSymbolAddress((void**)&wol,   g_wol);
    cudaGetSymbolAddress((void**)&w1h,   g_w1h);
    cudaGetSymbolAddress((void**)&w1l,   g_w1l);
    cudaGetSymbolAddress((void**)&w2h,   g_w2h);
    cudaGetSymbolAddress((void**)&w2l,   g_w2l);
    cudaGetSymbolAddress((void**)&whh,   g_whh);
    cudaGetSymbolAddress((void**)&whl,   g_whl);

    cudaFuncSetAttribute(gemm_big<true,  false, false>, cudaFuncAttributeMaxDynamicSharedMemorySize, BIG_SMEM);
    cudaFuncSetAttribute(gemm_big<true,  true,  true >, cudaFuncAttributeMaxDynamicSharedMemorySize, BIG_SMEM);
    cudaFuncSetAttribute(gemm_big<false, false, false>, cudaFuncAttributeMaxDynamicSharedMemorySize, BIG_SMEM);
    cudaFuncSetAttribute(gemm_sm<true, true>,  cudaFuncAttributeMaxDynamicSharedMemorySize, SM_SMEM);
    cudaFuncSetAttribute(attn_kernel, cudaFuncAttributeMaxDynamicSharedMemorySize, ATTN_SMEM);

    const int M = BB * TT;

    // [0] fused conversion
    {
        size_t total = 3 * (size_t)LL * CC * CC / 4 + (size_t)LL * CC * CC / 4 +
                       2 * ((size_t)LL * FF * CC / 4) + (size_t)VV * CC / 4 +
                       (size_t)LL * 3 * CC;
        convert_all<<<(int)((total + 255) / 256), 256>>>(
            Wq, Wk, Wv, Wo, W1, W2, head_w, bq, bk, bv,
            wqkvh, wqkvl, woh, wol, w1h, w1l, w2h, w2l, whh, whl, bqkv);
    }
    // [1] embed
    embed_kernel<<<(BB * TT * CC + 255) / 256, 256>>>(idx, tok, pos, x);

    for (int l = 0; l < LL; l++) {
        const size_t o3 = (size_t)l * 3 * CC * CC;
        const size_t o1 = (size_t)l * CC * CC;
        const size_t of = (size_t)l * FF * CC;

        // [2] ln, [3] gemm_big qkv, [4] attn, [5] gemm_sm  (l=0 → ncu window)
        ln_kernel<<<M, 256>>>(x, hh, hl, ln1w + (size_t)l * CC, ln1b + (size_t)l * CC);
        gemm_big<true, false, false><<<big_grid(M, 3 * CC), 256, BIG_SMEM>>>(
            hh, hl, wqkvh + o3, wqkvl + o3, bqkv + (size_t)l * 3 * CC,
            qkv, nullptr, nullptr, M, 3 * CC, CC);
        attn_kernel<<<dim3(TT / QT, BB * HH), 256, ATTN_SMEM>>>(qkv, yh, yl);
        gemm_sm<true, true><<<sm_grid(M, CC), 256, SM_SMEM>>>(
            yh, yl, woh + o1, wol + o1, bo + (size_t)l * CC, x, x, M, CC, CC);
        ln_kernel<<<M, 256>>>(x, hh, hl, ln2w + (size_t)l * CC, ln2b + (size_t)l * CC);
        gemm_big<true, true, true><<<big_grid(M, FF), 256, BIG_SMEM>>>(
            hh, hl, w1h + of, w1l + of, b1 + (size_t)l * FF,
            nullptr, h2h, h2l, M, FF, CC);
        gemm_sm<true, true><<<sm_grid(M, CC), 256, SM_SMEM>>>(
            h2h, h2l, w2h + of, w2l + of, b2 + (size_t)l * CC, x, x, M, CC, FF);
    }

    ln_kernel<<<M, 256>>>(x, hh, hl, lnfw, lnfb);
    gemm_big<false, false, false><<<big_grid(M, VV), 256, BIG_SMEM>>>(
        hh, hl, whh, whl, nullptr,
        out, nullptr, nullptr, M, VV, CC);
}